// round 3
// baseline (speedup 1.0000x reference)
#include <cuda_runtime.h>
#include <mma.h>
#include <math.h>

using namespace nvcuda;

#define CB 2
#define CT 8
#define CHEADS 12
#define CD 768
#define CDF 3072
#define CE 8
#define CN 196
#define CS 1568
#define CBS 3136           // B*S
#define CBSP 3200          // padded per-expert row stride (25*128)
#define C3D 2304

#define GEMM_SMEM_BYTES 67584   // 128*132*4 for C staging (>= A+B staging)

// ---------------- scratch (device globals; no allocation allowed) ----------------
__device__ float g_patches[CBS*CD];
__device__ float g_x[CBS*CD];
__device__ float g_h[CBS*CD];
__device__ float g_h2[CBS*CD];
__device__ float g_qkv[CBS*C3D];
__device__ float g_att[CBS*CD];
__device__ float g_he[(size_t)CE*CBSP*CDF];   // expert hidden, slot-indexed (padded)
__device__ float g_moe[(size_t)CE*CBSP*CD];   // expert output, slot-indexed (padded)
__device__ float g_tproj[CB*CD];
__device__ int   g_counts[CE];
__device__ int   g_tok[CE*CBS];              // slot -> token row
__device__ int   g_slot[CBS*2];              // token -> its 2 slots (padded index)
__device__ float g_gate[CBS*2];              // token -> its 2 gates

__device__ __forceinline__ float gelu_t(float x){
    return 0.5f*x*(1.0f + tanhf(0.7978845608028654f*(x + 0.044715f*x*x*x)));
}

// ---------------- patchify: video -> [BS, 768] patch vectors ----------------
__global__ __launch_bounds__(256) void patchify_k(const float* __restrict__ video,
                                                  float* __restrict__ out){
    int i = blockIdx.x*256 + threadIdx.x;
    if (i >= CBS*CD) return;
    int r = i / CD, pp = i % CD;
    int b = r / CS, s = r % CS;
    int t = s / CN, pi = s % CN;
    int ph = pi / 14, pw = pi % 14;
    int c = pp >> 8, rem = pp & 255, py = rem >> 4, px = rem & 15;
    size_t vi = ((((size_t)b*CT + t)*3 + c)*224 + (ph*16+py))*224 + (pw*16+px);
    out[i] = video[vi];
}

// ---------------- layernorm (one block per row, 768 cols) ----------------
__global__ __launch_bounds__(256) void ln_k(const float* __restrict__ x,
                                            const float* __restrict__ gs,
                                            const float* __restrict__ gb,
                                            float* __restrict__ out){
    int r = blockIdx.x;
    const float* xr = x + (size_t)r*CD;
    int d = threadIdx.x;
    float v0 = xr[d], v1 = xr[d+256], v2 = xr[d+512];
    float s = v0+v1+v2, sq = v0*v0+v1*v1+v2*v2;
    #pragma unroll
    for (int o=16;o;o>>=1){ s += __shfl_xor_sync(0xffffffffu,s,o); sq += __shfl_xor_sync(0xffffffffu,sq,o); }
    __shared__ float rs[8], rq[8];
    int w = threadIdx.x>>5;
    if ((threadIdx.x&31)==0){ rs[w]=s; rq[w]=sq; }
    __syncthreads();
    float ts=0.f, tq=0.f;
    #pragma unroll
    for (int i=0;i<8;i++){ ts+=rs[i]; tq+=rq[i]; }
    float mean = ts*(1.0f/CD);
    float var  = tq*(1.0f/CD) - mean*mean;
    float rstd = rsqrtf(var + 1e-5f);
    float* orow = out + (size_t)r*CD;
    orow[d]     = (v0-mean)*rstd*gs[d]     + gb[d];
    orow[d+256] = (v1-mean)*rstd*gs[d+256] + gb[d+256];
    orow[d+512] = (v2-mean)*rstd*gs[d+512] + gb[d+512];
}

// =====================================================================
// 3xTF32 tensor-core GEMM: C[M,N] = A[M,K] @ W[K,N] (+bias,+adds,gelu)
// a = hi + lo split; C += Ahi*Bhi + Ahi*Blo + Alo*Bhi  (near-fp32 accuracy)
// block tile 128x128, 8 warps of 64x32 (4x2 wmma m16n16k8 tiles), K-chunk 32
// =====================================================================
typedef wmma::fragment<wmma::matrix_a,16,16,8,wmma::precision::tf32,wmma::row_major> AFrag;
typedef wmma::fragment<wmma::matrix_b,16,16,8,wmma::precision::tf32,wmma::row_major> BFrag;
typedef wmma::fragment<wmma::accumulator,16,16,8,float> CFrag;

__device__ __forceinline__ void split_a(AFrag& hi, AFrag& lo){
    #pragma unroll
    for (int e=0;e<hi.num_elements;e++){
        float v = hi.x[e];
        float h = wmma::__float_to_tf32(v);
        hi.x[e] = h;
        lo.x[e] = wmma::__float_to_tf32(v - h);
    }
}
__device__ __forceinline__ void split_b(BFrag& hi, BFrag& lo){
    #pragma unroll
    for (int e=0;e<hi.num_elements;e++){
        float v = hi.x[e];
        float h = wmma::__float_to_tf32(v);
        hi.x[e] = h;
        lo.x[e] = wmma::__float_to_tf32(v - h);
    }
}

__global__ __launch_bounds__(256) void gemm_tc(
    int M, int N, int K,
    const float* __restrict__ A,
    const float* __restrict__ W,
    const float* __restrict__ bias,
    const float* __restrict__ addFull,   // optional residual [M,N]
    const float* __restrict__ addRow,    // optional, adds addRow[(row%CS)*N + col]
    float* __restrict__ C, int doGelu)
{
    extern __shared__ float sm[];
    float* As = sm;              // [128][36]
    float* Bs = sm + 128*36;     // [32][132]
    const int m0 = blockIdx.y*128, n0 = blockIdx.x*128;
    const int tid = threadIdx.x, wid = tid>>5;
    const int wm = (wid>>2)*64;   // warp row offset: 0 / 64
    const int wn = (wid&3)*32;    // warp col offset: 0/32/64/96

    CFrag cf[4][2];
    #pragma unroll
    for (int i=0;i<4;i++)
        #pragma unroll
        for (int j=0;j<2;j++) wmma::fill_fragment(cf[i][j], 0.f);

    for (int k0=0; k0<K; k0+=32){
        #pragma unroll
        for (int t=tid; t<128*8; t+=256){
            int r = t>>3, c4 = (t&7)*4;
            float4 v;
            int row = m0 + r;
            if (row < M) v = *(const float4*)(A + (size_t)row*K + k0 + c4);
            else         v = make_float4(0.f,0.f,0.f,0.f);
            *(float4*)(As + r*36 + c4) = v;
        }
        #pragma unroll
        for (int t=tid; t<32*32; t+=256){
            int r = t>>5, c4 = (t&31)*4;
            *(float4*)(Bs + r*132 + c4) = *(const float4*)(W + (size_t)(k0+r)*N + n0 + c4);
        }
        __syncthreads();
        #pragma unroll
        for (int kk=0; kk<32; kk+=8){
            AFrag ah[4], al[4];
            BFrag bh[2], bl[2];
            #pragma unroll
            for (int i=0;i<4;i++){
                wmma::load_matrix_sync(ah[i], As + (wm+i*16)*36 + kk, 36);
                split_a(ah[i], al[i]);
            }
            #pragma unroll
            for (int j=0;j<2;j++){
                wmma::load_matrix_sync(bh[j], Bs + kk*132 + wn + j*16, 132);
                split_b(bh[j], bl[j]);
            }
            #pragma unroll
            for (int i=0;i<4;i++)
                #pragma unroll
                for (int j=0;j<2;j++){
                    wmma::mma_sync(cf[i][j], ah[i], bl[j], cf[i][j]);
                    wmma::mma_sync(cf[i][j], al[i], bh[j], cf[i][j]);
                    wmma::mma_sync(cf[i][j], ah[i], bh[j], cf[i][j]);
                }
        }
        __syncthreads();
    }
    // epilogue: stage C tile in smem (reuses A/B space), fused bias/adds/gelu
    float* Cs = sm;  // [128][132]
    #pragma unroll
    for (int i=0;i<4;i++)
        #pragma unroll
        for (int j=0;j<2;j++)
            wmma::store_matrix_sync(Cs + (wm+i*16)*132 + wn + j*16, cf[i][j], 132, wmma::mem_row_major);
    __syncthreads();
    for (int t=tid; t<128*32; t+=256){
        int r = t>>5, c4 = (t&31)*4;
        int row = m0 + r;
        if (row >= M) continue;
        int col = n0 + c4;
        float4 v = *(float4*)(Cs + r*132 + c4);
        v.x += bias[col]; v.y += bias[col+1]; v.z += bias[col+2]; v.w += bias[col+3];
        if (addRow){
            const float* ar = addRow + (size_t)(row % CS)*N + col;
            v.x += ar[0]; v.y += ar[1]; v.z += ar[2]; v.w += ar[3];
        }
        if (addFull){
            const float* af2 = addFull + (size_t)row*N + col;
            v.x += af2[0]; v.y += af2[1]; v.z += af2[2]; v.w += af2[3];
        }
        if (doGelu){ v.x = gelu_t(v.x); v.y = gelu_t(v.y); v.z = gelu_t(v.z); v.w = gelu_t(v.w); }
        *(float4*)(C + (size_t)row*N + col) = v;
    }
}

// ---------------- expert 3xTF32 GEMM (grid.z = expert, count-guarded) ----------------
__global__ __launch_bounds__(256) void gemm_tc_expert(
    int N, int K,
    const float* __restrict__ A,            // stride K
    const int* __restrict__ tok_of_slot,    // null => A row = e*CBSP+m
    const float* __restrict__ Wl, size_t wstride,
    const float* __restrict__ bl, int bstride,
    float* __restrict__ C,                  // row = e*CBSP+m, stride N
    const int* __restrict__ counts, int doGelu)
{
    const int e = blockIdx.z;
    const int Me = counts[e];
    const int m0 = blockIdx.y*128;
    if (m0 >= Me) return;
    const float* W = Wl + (size_t)e*wstride;
    const float* bias = bl + (size_t)e*bstride;

    extern __shared__ float sm[];
    float* As = sm;
    float* Bs = sm + 128*36;
    const int n0 = blockIdx.x*128;
    const int tid = threadIdx.x, wid = tid>>5;
    const int wm = (wid>>2)*64;
    const int wn = (wid&3)*32;

    CFrag cf[4][2];
    #pragma unroll
    for (int i=0;i<4;i++)
        #pragma unroll
        for (int j=0;j<2;j++) wmma::fill_fragment(cf[i][j], 0.f);

    for (int k0=0; k0<K; k0+=32){
        #pragma unroll
        for (int t=tid; t<128*8; t+=256){
            int r = t>>3, c4 = (t&7)*4;
            int mm = m0 + r;
            int arow;
            if (tok_of_slot) arow = (mm < Me) ? tok_of_slot[e*CBS + mm] : 0;
            else             arow = e*CBSP + mm;
            *(float4*)(As + r*36 + c4) = *(const float4*)(A + (size_t)arow*K + k0 + c4);
        }
        #pragma unroll
        for (int t=tid; t<32*32; t+=256){
            int r = t>>5, c4 = (t&31)*4;
            *(float4*)(Bs + r*132 + c4) = *(const float4*)(W + (size_t)(k0+r)*N + n0 + c4);
        }
        __syncthreads();
        #pragma unroll
        for (int kk=0; kk<32; kk+=8){
            AFrag ah[4], al[4];
            BFrag bh[2], bl2[2];
            #pragma unroll
            for (int i=0;i<4;i++){
                wmma::load_matrix_sync(ah[i], As + (wm+i*16)*36 + kk, 36);
                split_a(ah[i], al[i]);
            }
            #pragma unroll
            for (int j=0;j<2;j++){
                wmma::load_matrix_sync(bh[j], Bs + kk*132 + wn + j*16, 132);
                split_b(bh[j], bl2[j]);
            }
            #pragma unroll
            for (int i=0;i<4;i++)
                #pragma unroll
                for (int j=0;j<2;j++){
                    wmma::mma_sync(cf[i][j], ah[i], bl2[j], cf[i][j]);
                    wmma::mma_sync(cf[i][j], al[i], bh[j], cf[i][j]);
                    wmma::mma_sync(cf[i][j], ah[i], bh[j], cf[i][j]);
                }
        }
        __syncthreads();
    }
    float* Cs = sm;
    #pragma unroll
    for (int i=0;i<4;i++)
        #pragma unroll
        for (int j=0;j<2;j++)
            wmma::store_matrix_sync(Cs + (wm+i*16)*132 + wn + j*16, cf[i][j], 132, wmma::mem_row_major);
    __syncthreads();
    for (int t=tid; t<128*32; t+=256){
        int r = t>>5, c4 = (t&31)*4;
        int mm = m0 + r;                 // up to 3199 < CBSP, always safe to store
        size_t crow = (size_t)(e*CBSP + mm);
        int col = n0 + c4;
        float4 v = *(float4*)(Cs + r*132 + c4);
        v.x += bias[col]; v.y += bias[col+1]; v.z += bias[col+2]; v.w += bias[col+3];
        if (doGelu){ v.x = gelu_t(v.x); v.y = gelu_t(v.y); v.z = gelu_t(v.z); v.w = gelu_t(v.w); }
        *(float4*)(C + crow*N + col) = v;
    }
}

// ---------------- flash-style attention: 16 queries/block, stream 32-key chunks ----------------
__global__ __launch_bounds__(256) void attn_k(const float* __restrict__ qkv,
                                              const float* __restrict__ tb,   // [HEADS,15] for layer l
                                              float* __restrict__ out){
    const int h = blockIdx.y, b = blockIdx.z;
    const int q0g = blockIdx.x * 16;
    __shared__ float Qs[16][64];
    __shared__ float Ks[32][65];
    __shared__ float Vs[32][64];
    __shared__ float Ps[8][2][32];
    __shared__ float tbs[15];
    int tid = threadIdx.x, lane = tid & 31, w = tid >> 5;
    if (tid < 15) tbs[tid] = tb[h*15 + tid];
    for (int i = tid; i < 16*64; i += 256){
        int qi = i >> 6, d = i & 63;
        Qs[qi][d] = qkv[(size_t)(b*CS + q0g + qi)*C3D + h*64 + d] * 0.125f;
    }
    __syncthreads();
    const int ql0 = w*2, ql1 = w*2+1;
    const int fq0 = (q0g + ql0)/CN, fq1 = (q0g + ql1)/CN;
    float m0=-1e30f, m1=-1e30f, l0=0.f, l1=0.f;
    float o00=0.f,o01=0.f,o10=0.f,o11=0.f;
    for (int c = 0; c < CS/32; c++){
        __syncthreads();
        for (int i = tid; i < 32*64; i += 256){
            int j = i >> 6, d = i & 63;
            size_t base = (size_t)(b*CS + c*32 + j)*C3D + h*64 + d;
            Ks[j][d] = qkv[base + CD];
            Vs[j][d] = qkv[base + 2*CD];
        }
        __syncthreads();
        int key = c*32 + lane;
        int fk = key/CN;
        float s0=0.f, s1=0.f;
        #pragma unroll
        for (int d=0; d<64; d++){
            float kv = Ks[lane][d];
            s0 += Qs[ql0][d]*kv;
            s1 += Qs[ql1][d]*kv;
        }
        s0 += tbs[fq0 - fk + 7];
        s1 += tbs[fq1 - fk + 7];
        float mx0=s0, mx1=s1;
        #pragma unroll
        for (int o=16;o;o>>=1){ mx0=fmaxf(mx0,__shfl_xor_sync(0xffffffffu,mx0,o)); mx1=fmaxf(mx1,__shfl_xor_sync(0xffffffffu,mx1,o)); }
        float mn0 = fmaxf(m0,mx0), mn1 = fmaxf(m1,mx1);
        float p0 = expf(s0-mn0), p1 = expf(s1-mn1);
        float sp0=p0, sp1=p1;
        #pragma unroll
        for (int o=16;o;o>>=1){ sp0+=__shfl_xor_sync(0xffffffffu,sp0,o); sp1+=__shfl_xor_sync(0xffffffffu,sp1,o); }
        float c0 = expf(m0-mn0), c1 = expf(m1-mn1);
        l0 = l0*c0 + sp0;  l1 = l1*c1 + sp1;
        m0 = mn0; m1 = mn1;
        o00*=c0; o01*=c0; o10*=c1; o11*=c1;
        Ps[w][0][lane]=p0; Ps[w][1][lane]=p1;
        __syncwarp();
        #pragma unroll
        for (int j=0;j<32;j++){
            float v0 = Vs[j][2*lane], v1 = Vs[j][2*lane+1];
            float pa = Ps[w][0][j], pb = Ps[w][1][j];
            o00 += pa*v0; o01 += pa*v1; o10 += pb*v0; o11 += pb*v1;
        }
    }
    float inv0 = 1.f/l0, inv1 = 1.f/l1;
    size_t r0 = (size_t)(b*CS + q0g + ql0)*CD + h*64 + 2*lane;
    size_t r1 = (size_t)(b*CS + q0g + ql1)*CD + h*64 + 2*lane;
    out[r0] = o00*inv0; out[r0+1] = o01*inv0;
    out[r1] = o10*inv1; out[r1+1] = o11*inv1;
}

// ---------------- text projection (tiny) ----------------
__global__ __launch_bounds__(256) void textproj_k(const float* __restrict__ ts,
                                                  const float* __restrict__ wt,
                                                  const float* __restrict__ bt,
                                                  float* __restrict__ out){
    int i = blockIdx.x*256 + threadIdx.x;
    if (i >= CB*CD) return;
    int b = i/CD, d = i%CD;
    float a = bt[d];
    for (int k=0;k<CD;k++) a += ts[b*CD+k]*wt[(size_t)k*CD+d];
    out[i] = a;
}

__global__ void zero8_k(int* c){ if (threadIdx.x < CE) c[threadIdx.x] = 0; }

// ---------------- router: logits, top-2, gates, slot assignment ----------------
__global__ __launch_bounds__(256) void router_k(const float* __restrict__ h2,
                                                const float* __restrict__ tproj,
                                                const float* __restrict__ wr,    // [768,8]
                                                int* __restrict__ counts,
                                                int* __restrict__ tok_of_slot,
                                                int* __restrict__ slot_of,
                                                float* __restrict__ gatev){
    int w = threadIdx.x >> 5, lane = threadIdx.x & 31;
    int r = blockIdx.x*8 + w;
    int b = r / CS;
    float acc[8] = {};
    for (int d = lane; d < CD; d += 32){
        float rv = h2[(size_t)r*CD + d] + tproj[b*CD + d];
        #pragma unroll
        for (int e=0;e<8;e++) acc[e] += rv * wr[d*8 + e];
    }
    #pragma unroll
    for (int e=0;e<8;e++)
        #pragma unroll
        for (int o=16;o;o>>=1) acc[e] += __shfl_xor_sync(0xffffffffu, acc[e], o);
    if (lane == 0){
        int i0 = 0; float v0 = acc[0];
        #pragma unroll
        for (int e=1;e<8;e++) if (acc[e] > v0){ v0=acc[e]; i0=e; }
        int i1 = -1; float v1 = -1e30f;
        #pragma unroll
        for (int e=0;e<8;e++) if (e!=i0 && acc[e] > v1){ v1=acc[e]; i1=e; }
        float g0 = 1.f/(1.f + expf(v1 - v0));
        float g1 = 1.f - g0;
        int p0 = atomicAdd(&counts[i0], 1);
        tok_of_slot[i0*CBS + p0] = r; slot_of[r*2]   = i0*CBSP + p0; gatev[r*2]   = g0;
        int p1 = atomicAdd(&counts[i1], 1);
        tok_of_slot[i1*CBS + p1] = r; slot_of[r*2+1] = i1*CBSP + p1; gatev[r*2+1] = g1;
    }
}

// ---------------- combine: x += gate0*moe[slot0] + gate1*moe[slot1] ----------------
__global__ __launch_bounds__(256) void combine_k(float* __restrict__ x,
                                                 const float* __restrict__ moe,
                                                 const int* __restrict__ slot_of,
                                                 const float* __restrict__ gatev){
    int i = blockIdx.x*256 + threadIdx.x;
    if (i >= CBS*CD) return;
    int r = i / CD, d = i % CD;
    float v = x[i];
    v += gatev[r*2]   * moe[(size_t)slot_of[r*2]*CD   + d];
    v += gatev[r*2+1] * moe[(size_t)slot_of[r*2+1]*CD + d];
    x[i] = v;
}

// =============================== host ===============================
extern "C" void kernel_launch(void* const* d_in, const int* in_sizes, int n_in,
                              void* d_out, int out_size){
    const float* video   = (const float*)d_in[0];
    const float* text    = (const float*)d_in[1];
    const float* patch_w = (const float*)d_in[2];
    const float* patch_b = (const float*)d_in[3];
    const float* pos_emb = (const float*)d_in[4];
    const float* ln1s    = (const float*)d_in[5];
    const float* ln1b    = (const float*)d_in[6];
    const float* wqkv    = (const float*)d_in[7];
    const float* bqkv    = (const float*)d_in[8];
    const float* wo      = (const float*)d_in[9];
    const float* bo      = (const float*)d_in[10];
    const float* tbias   = (const float*)d_in[11];
    const float* ln2s    = (const float*)d_in[12];
    const float* ln2b    = (const float*)d_in[13];
    const float* wtext   = (const float*)d_in[14];
    const float* btext   = (const float*)d_in[15];
    const float* wrouter = (const float*)d_in[16];
    const float* w1      = (const float*)d_in[17];
    const float* b1      = (const float*)d_in[18];
    const float* w2      = (const float*)d_in[19];
    const float* b2      = (const float*)d_in[20];
    const float* lnfs    = (const float*)d_in[21];
    const float* lnfb    = (const float*)d_in[22];

    float *p_patches,*p_x,*p_h,*p_h2,*p_qkv,*p_att,*p_he,*p_moe,*p_tproj,*p_gate;
    int *p_counts,*p_tok,*p_slot;
    cudaGetSymbolAddress((void**)&p_patches, g_patches);
    cudaGetSymbolAddress((void**)&p_x,       g_x);
    cudaGetSymbolAddress((void**)&p_h,       g_h);
    cudaGetSymbolAddress((void**)&p_h2,      g_h2);
    cudaGetSymbolAddress((void**)&p_qkv,     g_qkv);
    cudaGetSymbolAddress((void**)&p_att,     g_att);
    cudaGetSymbolAddress((void**)&p_he,      g_he);
    cudaGetSymbolAddress((void**)&p_moe,     g_moe);
    cudaGetSymbolAddress((void**)&p_tproj,   g_tproj);
    cudaGetSymbolAddress((void**)&p_counts,  g_counts);
    cudaGetSymbolAddress((void**)&p_tok,     g_tok);
    cudaGetSymbolAddress((void**)&p_slot,    g_slot);
    cudaGetSymbolAddress((void**)&p_gate,    g_gate);

    cudaFuncSetAttribute(gemm_tc, cudaFuncAttributeMaxDynamicSharedMemorySize, GEMM_SMEM_BYTES);
    cudaFuncSetAttribute(gemm_tc_expert, cudaFuncAttributeMaxDynamicSharedMemorySize, GEMM_SMEM_BYTES);

    const int EW = (CBS*CD + 255)/256;   // elementwise grid
    const int MB = (CBS + 127)/128;      // 25 row-blocks

    // embed
    patchify_k<<<EW,256>>>(video, p_patches);
    gemm_tc<<<dim3(CD/128, MB),256,GEMM_SMEM_BYTES>>>(CBS, CD, CD, p_patches, patch_w, patch_b,
                                                      nullptr, pos_emb, p_x, 0);

    for (int l = 0; l < 4; l++){
        // attention
        ln_k<<<CBS,256>>>(p_x, ln1s + l*CD, ln1b + l*CD, p_h);
        gemm_tc<<<dim3(C3D/128, MB),256,GEMM_SMEM_BYTES>>>(CBS, C3D, CD, p_h,
                                             wqkv + (size_t)l*CD*C3D, bqkv + l*C3D,
                                             nullptr, nullptr, p_qkv, 0);
        attn_k<<<dim3(CS/16, CHEADS, CB),256>>>(p_qkv, tbias + l*CHEADS*(2*CT-1), p_att);
        gemm_tc<<<dim3(CD/128, MB),256,GEMM_SMEM_BYTES>>>(CBS, CD, CD, p_att,
                                            wo + (size_t)l*CD*CD, bo + l*CD,
                                            p_x, nullptr, p_x, 0);
        // MoE
        ln_k<<<CBS,256>>>(p_x, ln2s + l*CD, ln2b + l*CD, p_h2);
        textproj_k<<<(CB*CD+255)/256,256>>>(text, wtext + (size_t)l*CD*CD, btext + l*CD, p_tproj);
        zero8_k<<<1,CE>>>(p_counts);
        router_k<<<CBS/8,256>>>(p_h2, p_tproj, wrouter + (size_t)l*CD*CE,
                                p_counts, p_tok, p_slot, p_gate);
        gemm_tc_expert<<<dim3(CDF/128, MB, CE),256,GEMM_SMEM_BYTES>>>(CDF, CD, p_h2, p_tok,
                                                        w1 + (size_t)l*CE*CD*CDF, (size_t)CD*CDF,
                                                        b1 + (size_t)l*CE*CDF, CDF,
                                                        p_he, p_counts, 1);
        gemm_tc_expert<<<dim3(CD/128, MB, CE),256,GEMM_SMEM_BYTES>>>(CD, CDF, p_he, nullptr,
                                                       w2 + (size_t)l*CE*CDF*CD, (size_t)CDF*CD,
                                                       b2 + (size_t)l*CE*CD, CD,
                                                       p_moe, p_counts, 0);
        combine_k<<<EW,256>>>(p_x, p_moe, p_slot, p_gate);
    }

    ln_k<<<CBS,256>>>(p_x, lnfs, lnfb, (float*)d_out);
}

// round 9
// speedup vs baseline: 1.3770x; 1.3770x over previous
#include <cuda_runtime.h>
#include <math.h>

#define CB 2
#define CT 8
#define CHEADS 12
#define CD 768
#define CDF 3072
#define CE 8
#define CN 196
#define CS 1568
#define CBS 3136           // B*S
#define CBSP 3200          // padded per-expert row stride (25*128)
#define C3D 2304

// smem: Ah[128][36] + Al[128][36] + Bh[32][136] + Bl[32][136] floats
#define SM_A  (128*36)
#define SM_B  (32*136)
#define TC_SMEM_FLOATS (2*SM_A + 2*SM_B)
#define TC_SMEM_BYTES  (TC_SMEM_FLOATS*4)

// ---------------- scratch (device globals; no allocation allowed) ----------------
__device__ float g_patches[CBS*CD];
__device__ float g_x[CBS*CD];
__device__ float g_h[CBS*CD];
__device__ float g_h2[CBS*CD];
__device__ float g_qkv[CBS*C3D];
__device__ float g_att[CBS*CD];
__device__ float g_he[(size_t)CE*CBSP*CDF];   // expert hidden, slot-indexed (padded)
__device__ float g_moe[(size_t)CE*CBSP*CD];   // expert output, slot-indexed (padded)
__device__ float g_tproj[CB*CD];
__device__ int   g_counts[CE];
__device__ int   g_tok[CE*CBS];              // slot -> token row
__device__ int   g_slot[CBS*2];              // token -> its 2 slots (padded index)
__device__ float g_gate[CBS*2];              // token -> its 2 gates

__device__ __forceinline__ float gelu_t(float x){
    return 0.5f*x*(1.0f + tanhf(0.7978845608028654f*(x + 0.044715f*x*x*x)));
}
__device__ __forceinline__ float to_tf32(float v){
    float r; asm("cvt.rna.tf32.f32 %0, %1;" : "=f"(r) : "f"(v)); return r;
}

#define MMA_TF32(c, A0,A1,A2,A3, B0,B1) \
    asm volatile("mma.sync.aligned.m16n8k8.row.col.f32.tf32.tf32.f32 " \
        "{%0,%1,%2,%3}, {%4,%5,%6,%7}, {%8,%9}, {%0,%1,%2,%3};" \
        : "+f"((c)[0]),"+f"((c)[1]),"+f"((c)[2]),"+f"((c)[3]) \
        : "r"(A0),"r"(A1),"r"(A2),"r"(A3),"r"(B0),"r"(B1))

// ---------------- patchify ----------------
__global__ __launch_bounds__(256) void patchify_k(const float* __restrict__ video,
                                                  float* __restrict__ out){
    int i = blockIdx.x*256 + threadIdx.x;
    if (i >= CBS*CD) return;
    int r = i / CD, pp = i % CD;
    int b = r / CS, s = r % CS;
    int t = s / CN, pi = s % CN;
    int ph = pi / 14, pw = pi % 14;
    int c = pp >> 8, rem = pp & 255, py = rem >> 4, px = rem & 15;
    size_t vi = ((((size_t)b*CT + t)*3 + c)*224 + (ph*16+py))*224 + (pw*16+px);
    out[i] = video[vi];
}

// ---------------- layernorm ----------------
__global__ __launch_bounds__(256) void ln_k(const float* __restrict__ x,
                                            const float* __restrict__ gs,
                                            const float* __restrict__ gb,
                                            float* __restrict__ out){
    int r = blockIdx.x;
    const float* xr = x + (size_t)r*CD;
    int d = threadIdx.x;
    float v0 = xr[d], v1 = xr[d+256], v2 = xr[d+512];
    float s = v0+v1+v2, sq = v0*v0+v1*v1+v2*v2;
    #pragma unroll
    for (int o=16;o;o>>=1){ s += __shfl_xor_sync(0xffffffffu,s,o); sq += __shfl_xor_sync(0xffffffffu,sq,o); }
    __shared__ float rs[8], rq[8];
    int w = threadIdx.x>>5;
    if ((threadIdx.x&31)==0){ rs[w]=s; rq[w]=sq; }
    __syncthreads();
    float ts=0.f, tq=0.f;
    #pragma unroll
    for (int i=0;i<8;i++){ ts+=rs[i]; tq+=rq[i]; }
    float mean = ts*(1.0f/CD);
    float var  = tq*(1.0f/CD) - mean*mean;
    float rstd = rsqrtf(var + 1e-5f);
    float* orow = out + (size_t)r*CD;
    orow[d]     = (v0-mean)*rstd*gs[d]     + gb[d];
    orow[d+256] = (v1-mean)*rstd*gs[d+256] + gb[d+256];
    orow[d+512] = (v2-mean)*rstd*gs[d+512] + gb[d+512];
}

// =====================================================================
// 3xTF32 mma.sync GEMM: C[M,N] = A @ W (+bias, +residual, +posemb, gelu)
// Block 256 thr, tile 128x128, K-chunk 32. Warp = 64rows x 32cols.
// hi/lo split precomputed into smem. 2 CTAs/SM via launch_bounds.
// Dense mode: counts==null. Expert: rows = e*CBSP+m, A via tok (w1) or direct (w2).
// =====================================================================
__global__ __launch_bounds__(256,2) void tc_gemm(
    int M, int N, int K,
    const float* __restrict__ A,
    const float* __restrict__ Wl, size_t wstride,
    const float* __restrict__ bl, int bstride,
    const float* __restrict__ addFull,
    const float* __restrict__ addRow,
    float* __restrict__ C,
    const int* __restrict__ tok,
    const int* __restrict__ counts,
    int doGelu)
{
    extern __shared__ float smf[];
    float* Ah = smf;
    float* Al = smf + SM_A;
    float* Bh = smf + 2*SM_A;
    float* Bl = smf + 2*SM_A + SM_B;

    const int e = blockIdx.z;
    int Me = M;
    const float* W = Wl;
    const float* bias = bl;
    if (counts){
        Me = counts[e];
        W = Wl + (size_t)e*wstride;
        bias = bl + (size_t)e*bstride;
    }
    const int m0 = blockIdx.y*128;
    if (m0 >= Me) return;
    const int n0 = blockIdx.x*128;
    const int tid = threadIdx.x, wid = tid>>5, lane = tid&31;
    const int wm = (wid>>2)*64;    // 0 / 64
    const int wn = (wid&3)*32;     // 0/32/64/96
    const int g = lane>>2, t4 = lane&3;

    // loader coords
    const int rowA = tid>>1, segA = (tid&1)*16;   // A: 128 rows x 32 cols
    const int rowB = tid>>3, segB = (tid&7)*16;   // B: 32 rows x 128 cols

    size_t arow;
    {
        int mm = m0 + rowA;
        if (tok)         arow = (size_t)tok[e*CBS + (mm < Me ? mm : 0)];
        else if (counts) arow = (size_t)e*CBSP + mm;             // padded scratch, safe
        else             arow = (size_t)(mm < M ? mm : (M-1));
    }
    const float* apBase = A + arow*(size_t)K + segA;
    const float* bpBase = W + (size_t)rowB*N + n0 + segB;

    float acc[4][4][4];
    #pragma unroll
    for (int i=0;i<4;i++)
        #pragma unroll
        for (int j=0;j<4;j++)
            #pragma unroll
            for (int q=0;q<4;q++) acc[i][j][q] = 0.f;

    const int nc = K/32;
    float4 a4[4], b4[4];
    #pragma unroll
    for (int i=0;i<4;i++) a4[i] = *(const float4*)(apBase + i*4);
    #pragma unroll
    for (int i=0;i<4;i++) b4[i] = *(const float4*)(bpBase + i*4);

    for (int c = 0; c < nc; c++){
        if (c) __syncthreads();   // previous compute done reading smem
        // split + store to smem
        #pragma unroll
        for (int i=0;i<4;i++){
            float4 v = a4[i], h, l;
            h.x = to_tf32(v.x); l.x = to_tf32(v.x - h.x);
            h.y = to_tf32(v.y); l.y = to_tf32(v.y - h.y);
            h.z = to_tf32(v.z); l.z = to_tf32(v.z - h.z);
            h.w = to_tf32(v.w); l.w = to_tf32(v.w - h.w);
            int idx = rowA*36 + segA + i*4;
            *(float4*)(Ah + idx) = h;
            *(float4*)(Al + idx) = l;
        }
        #pragma unroll
        for (int i=0;i<4;i++){
            float4 v = b4[i], h, l;
            h.x = to_tf32(v.x); l.x = to_tf32(v.x - h.x);
            h.y = to_tf32(v.y); l.y = to_tf32(v.y - h.y);
            h.z = to_tf32(v.z); l.z = to_tf32(v.z - h.z);
            h.w = to_tf32(v.w); l.w = to_tf32(v.w - h.w);
            int idx = rowB*136 + segB + i*4;
            *(float4*)(Bh + idx) = h;
            *(float4*)(Bl + idx) = l;
        }
        __syncthreads();
        // prefetch next chunk (latency hidden by MMA phase)
        if (c+1 < nc){
            const float* ap = apBase + (c+1)*32;
            const float* bp = bpBase + (size_t)(c+1)*32*N;
            #pragma unroll
            for (int i=0;i<4;i++) a4[i] = *(const float4*)(ap + i*4);
            #pragma unroll
            for (int i=0;i<4;i++) b4[i] = *(const float4*)(bp + i*4);
        }
        // compute: 4 k-steps of 8
        #pragma unroll
        for (int ks=0; ks<4; ks++){
            unsigned ahr[4][4], alr[4][4];
            #pragma unroll
            for (int mi=0;mi<4;mi++){
                int r0 = (wm + mi*16 + g)*36 + ks*8 + t4;
                int r1 = r0 + 8*36;
                ahr[mi][0] = __float_as_uint(Ah[r0]);
                ahr[mi][1] = __float_as_uint(Ah[r1]);
                ahr[mi][2] = __float_as_uint(Ah[r0+4]);
                ahr[mi][3] = __float_as_uint(Ah[r1+4]);
                alr[mi][0] = __float_as_uint(Al[r0]);
                alr[mi][1] = __float_as_uint(Al[r1]);
                alr[mi][2] = __float_as_uint(Al[r0+4]);
                alr[mi][3] = __float_as_uint(Al[r1+4]);
            }
            #pragma unroll
            for (int ni=0;ni<4;ni++){
                int b0i = (ks*8 + t4)*136 + wn + ni*8 + g;
                int b1i = b0i + 4*136;
                unsigned bh0 = __float_as_uint(Bh[b0i]);
                unsigned bh1 = __float_as_uint(Bh[b1i]);
                unsigned bl0 = __float_as_uint(Bl[b0i]);
                unsigned bl1 = __float_as_uint(Bl[b1i]);
                #pragma unroll
                for (int mi=0;mi<4;mi++){
                    MMA_TF32(acc[mi][ni], ahr[mi][0],ahr[mi][1],ahr[mi][2],ahr[mi][3], bl0,bl1);
                    MMA_TF32(acc[mi][ni], alr[mi][0],alr[mi][1],alr[mi][2],alr[mi][3], bh0,bh1);
                    MMA_TF32(acc[mi][ni], ahr[mi][0],ahr[mi][1],ahr[mi][2],ahr[mi][3], bh0,bh1);
                }
            }
        }
    }

    // epilogue: direct gmem stores, fused bias/adds/gelu
    #pragma unroll
    for (int mi=0;mi<4;mi++){
        #pragma unroll
        for (int half=0; half<2; half++){
            int mm = m0 + wm + mi*16 + g + half*8;
            if (!counts && mm >= M) continue;
            size_t crow = counts ? ((size_t)e*CBSP + mm) : (size_t)mm;
            float* cp = C + crow*N;
            const float* afp = addFull ? (addFull + crow*N) : (const float*)0;
            const float* arp = addRow  ? (addRow + (size_t)(mm % CS)*N) : (const float*)0;
            #pragma unroll
            for (int ni=0;ni<4;ni++){
                int col = n0 + wn + ni*8 + 2*t4;
                float v0 = acc[mi][ni][half*2+0] + bias[col];
                float v1 = acc[mi][ni][half*2+1] + bias[col+1];
                if (arp){ v0 += arp[col]; v1 += arp[col+1]; }
                if (afp){ v0 += afp[col]; v1 += afp[col+1]; }
                if (doGelu){ v0 = gelu_t(v0); v1 = gelu_t(v1); }
                float2 vv; vv.x = v0; vv.y = v1;
                *(float2*)(cp + col) = vv;
            }
        }
    }
}

// ---------------- flash-style attention (SIMT) ----------------
__global__ __launch_bounds__(256) void attn_k(const float* __restrict__ qkv,
                                              const float* __restrict__ tb,
                                              float* __restrict__ out){
    const int h = blockIdx.y, b = blockIdx.z;
    const int q0g = blockIdx.x * 16;
    __shared__ float Qs[16][64];
    __shared__ float Ks[32][65];
    __shared__ float Vs[32][64];
    __shared__ float Ps[8][2][32];
    __shared__ float tbs[15];
    int tid = threadIdx.x, lane = tid & 31, w = tid >> 5;
    if (tid < 15) tbs[tid] = tb[h*15 + tid];
    for (int i = tid; i < 16*64; i += 256){
        int qi = i >> 6, d = i & 63;
        Qs[qi][d] = qkv[(size_t)(b*CS + q0g + qi)*C3D + h*64 + d] * 0.125f;
    }
    __syncthreads();
    const int ql0 = w*2, ql1 = w*2+1;
    const int fq0 = (q0g + ql0)/CN, fq1 = (q0g + ql1)/CN;
    float m0=-1e30f, m1=-1e30f, l0=0.f, l1=0.f;
    float o00=0.f,o01=0.f,o10=0.f,o11=0.f;
    for (int c = 0; c < CS/32; c++){
        __syncthreads();
        for (int i = tid; i < 32*64; i += 256){
            int j = i >> 6, d = i & 63;
            size_t base = (size_t)(b*CS + c*32 + j)*C3D + h*64 + d;
            Ks[j][d] = qkv[base + CD];
            Vs[j][d] = qkv[base + 2*CD];
        }
        __syncthreads();
        int key = c*32 + lane;
        int fk = key/CN;
        float s0=0.f, s1=0.f;
        #pragma unroll
        for (int d=0; d<64; d++){
            float kv = Ks[lane][d];
            s0 += Qs[ql0][d]*kv;
            s1 += Qs[ql1][d]*kv;
        }
        s0 += tbs[fq0 - fk + 7];
        s1 += tbs[fq1 - fk + 7];
        float mx0=s0, mx1=s1;
        #pragma unroll
        for (int o=16;o;o>>=1){ mx0=fmaxf(mx0,__shfl_xor_sync(0xffffffffu,mx0,o)); mx1=fmaxf(mx1,__shfl_xor_sync(0xffffffffu,mx1,o)); }
        float mn0 = fmaxf(m0,mx0), mn1 = fmaxf(m1,mx1);
        float p0 = expf(s0-mn0), p1 = expf(s1-mn1);
        float sp0=p0, sp1=p1;
        #pragma unroll
        for (int o=16;o;o>>=1){ sp0+=__shfl_xor_sync(0xffffffffu,sp0,o); sp1+=__shfl_xor_sync(0xffffffffu,sp1,o); }
        float c0 = expf(m0-mn0), c1 = expf(m1-mn1);
        l0 = l0*c0 + sp0;  l1 = l1*c1 + sp1;
        m0 = mn0; m1 = mn1;
        o00*=c0; o01*=c0; o10*=c1; o11*=c1;
        Ps[w][0][lane]=p0; Ps[w][1][lane]=p1;
        __syncwarp();
        #pragma unroll
        for (int j=0;j<32;j++){
            float v0 = Vs[j][2*lane], v1 = Vs[j][2*lane+1];
            float pa = Ps[w][0][j], pb = Ps[w][1][j];
            o00 += pa*v0; o01 += pa*v1; o10 += pb*v0; o11 += pb*v1;
        }
    }
    float inv0 = 1.f/l0, inv1 = 1.f/l1;
    size_t r0 = (size_t)(b*CS + q0g + ql0)*CD + h*64 + 2*lane;
    size_t r1 = (size_t)(b*CS + q0g + ql1)*CD + h*64 + 2*lane;
    out[r0] = o00*inv0; out[r0+1] = o01*inv0;
    out[r1] = o10*inv1; out[r1+1] = o11*inv1;
}

// ---------------- text projection (tiny) ----------------
__global__ __launch_bounds__(256) void textproj_k(const float* __restrict__ ts,
                                                  const float* __restrict__ wt,
                                                  const float* __restrict__ bt,
                                                  float* __restrict__ out){
    int i = blockIdx.x*256 + threadIdx.x;
    if (i >= CB*CD) return;
    int b = i/CD, d = i%CD;
    float a = bt[d];
    for (int k=0;k<CD;k++) a += ts[b*CD+k]*wt[(size_t)k*CD+d];
    out[i] = a;
}

__global__ void zero8_k(int* c){ if (threadIdx.x < CE) c[threadIdx.x] = 0; }

// ---------------- router ----------------
__global__ __launch_bounds__(256) void router_k(const float* __restrict__ h2,
                                                const float* __restrict__ tproj,
                                                const float* __restrict__ wr,
                                                int* __restrict__ counts,
                                                int* __restrict__ tok_of_slot,
                                                int* __restrict__ slot_of,
                                                float* __restrict__ gatev){
    int w = threadIdx.x >> 5, lane = threadIdx.x & 31;
    int r = blockIdx.x*8 + w;
    int b = r / CS;
    float acc[8] = {};
    for (int d = lane; d < CD; d += 32){
        float rv = h2[(size_t)r*CD + d] + tproj[b*CD + d];
        #pragma unroll
        for (int e=0;e<8;e++) acc[e] += rv * wr[d*8 + e];
    }
    #pragma unroll
    for (int e=0;e<8;e++)
        #pragma unroll
        for (int o=16;o;o>>=1) acc[e] += __shfl_xor_sync(0xffffffffu, acc[e], o);
    if (lane == 0){
        int i0 = 0; float v0 = acc[0];
        #pragma unroll
        for (int e=1;e<8;e++) if (acc[e] > v0){ v0=acc[e]; i0=e; }
        int i1 = -1; float v1 = -1e30f;
        #pragma unroll
        for (int e=0;e<8;e++) if (e!=i0 && acc[e] > v1){ v1=acc[e]; i1=e; }
        float g0 = 1.f/(1.f + expf(v1 - v0));
        float g1 = 1.f - g0;
        int p0 = atomicAdd(&counts[i0], 1);
        tok_of_slot[i0*CBS + p0] = r; slot_of[r*2]   = i0*CBSP + p0; gatev[r*2]   = g0;
        int p1 = atomicAdd(&counts[i1], 1);
        tok_of_slot[i1*CBS + p1] = r; slot_of[r*2+1] = i1*CBSP + p1; gatev[r*2+1] = g1;
    }
}

// ---------------- combine ----------------
__global__ __launch_bounds__(256) void combine_k(float* __restrict__ x,
                                                 const float* __restrict__ moe,
                                                 const int* __restrict__ slot_of,
                                                 const float* __restrict__ gatev){
    int i = blockIdx.x*256 + threadIdx.x;
    if (i >= CBS*CD) return;
    int r = i / CD, d = i % CD;
    float v = x[i];
    v += gatev[r*2]   * moe[(size_t)slot_of[r*2]*CD   + d];
    v += gatev[r*2+1] * moe[(size_t)slot_of[r*2+1]*CD + d];
    x[i] = v;
}

// =============================== host ===============================
extern "C" void kernel_launch(void* const* d_in, const int* in_sizes, int n_in,
                              void* d_out, int out_size){
    const float* video   = (const float*)d_in[0];
    const float* text    = (const float*)d_in[1];
    const float* patch_w = (const float*)d_in[2];
    const float* patch_b = (const float*)d_in[3];
    const float* pos_emb = (const float*)d_in[4];
    const float* ln1s    = (const float*)d_in[5];
    const float* ln1b    = (const float*)d_in[6];
    const float* wqkv    = (const float*)d_in[7];
    const float* bqkv    = (const float*)d_in[8];
    const float* wo      = (const float*)d_in[9];
    const float* bo      = (const float*)d_in[10];
    const float* tbias   = (const float*)d_in[11];
    const float* ln2s    = (const float*)d_in[12];
    const float* ln2b    = (const float*)d_in[13];
    const float* wtext   = (const float*)d_in[14];
    const float* btext   = (const float*)d_in[15];
    const float* wrouter = (const float*)d_in[16];
    const float* w1      = (const float*)d_in[17];
    const float* b1      = (const float*)d_in[18];
    const float* w2      = (const float*)d_in[19];
    const float* b2      = (const float*)d_in[20];
    const float* lnfs    = (const float*)d_in[21];
    const float* lnfb    = (const float*)d_in[22];

    float *p_patches,*p_x,*p_h,*p_h2,*p_qkv,*p_att,*p_he,*p_moe,*p_tproj,*p_gate;
    int *p_counts,*p_tok,*p_slot;
    cudaGetSymbolAddress((void**)&p_patches, g_patches);
    cudaGetSymbolAddress((void**)&p_x,       g_x);
    cudaGetSymbolAddress((void**)&p_h,       g_h);
    cudaGetSymbolAddress((void**)&p_h2,      g_h2);
    cudaGetSymbolAddress((void**)&p_qkv,     g_qkv);
    cudaGetSymbolAddress((void**)&p_att,     g_att);
    cudaGetSymbolAddress((void**)&p_he,      g_he);
    cudaGetSymbolAddress((void**)&p_moe,     g_moe);
    cudaGetSymbolAddress((void**)&p_tproj,   g_tproj);
    cudaGetSymbolAddress((void**)&p_counts,  g_counts);
    cudaGetSymbolAddress((void**)&p_tok,     g_tok);
    cudaGetSymbolAddress((void**)&p_slot,    g_slot);
    cudaGetSymbolAddress((void**)&p_gate,    g_gate);

    cudaFuncSetAttribute(tc_gemm, cudaFuncAttributeMaxDynamicSharedMemorySize, TC_SMEM_BYTES);

    const int EW = (CBS*CD + 255)/256;
    const int MB = (CBS + 127)/128;      // 25

    // embed
    patchify_k<<<EW,256>>>(video, p_patches);
    tc_gemm<<<dim3(CD/128, MB, 1),256,TC_SMEM_BYTES>>>(
        CBS, CD, CD, p_patches, patch_w, 0, patch_b, 0,
        nullptr, pos_emb, p_x, nullptr, nullptr, 0);

    for (int l = 0; l < 4; l++){
        // attention
        ln_k<<<CBS,256>>>(p_x, ln1s + l*CD, ln1b + l*CD, p_h);
        tc_gemm<<<dim3(C3D/128, MB, 1),256,TC_SMEM_BYTES>>>(
            CBS, C3D, CD, p_h, wqkv + (size_t)l*CD*C3D, 0, bqkv + l*C3D, 0,
            nullptr, nullptr, p_qkv, nullptr, nullptr, 0);
        attn_k<<<dim3(CS/16, CHEADS, CB),256>>>(p_qkv, tbias + l*CHEADS*(2*CT-1), p_att);
        tc_gemm<<<dim3(CD/128, MB, 1),256,TC_SMEM_BYTES>>>(
            CBS, CD, CD, p_att, wo + (size_t)l*CD*CD, 0, bo + l*CD, 0,
            p_x, nullptr, p_x, nullptr, nullptr, 0);
        // MoE
        ln_k<<<CBS,256>>>(p_x, ln2s + l*CD, ln2b + l*CD, p_h2);
        textproj_k<<<(CB*CD+255)/256,256>>>(text, wtext + (size_t)l*CD*CD, btext + l*CD, p_tproj);
        zero8_k<<<1,CE>>>(p_counts);
        router_k<<<CBS/8,256>>>(p_h2, p_tproj, wrouter + (size_t)l*CD*CE,
                                p_counts, p_tok, p_slot, p_gate);
        tc_gemm<<<dim3(CDF/128, MB, CE),256,TC_SMEM_BYTES>>>(
            CBS, CDF, CD, p_h2, w1 + (size_t)l*CE*CD*CDF, (size_t)CD*CDF,
            b1 + (size_t)l*CE*CDF, CDF,
            nullptr, nullptr, p_he, p_tok, p_counts, 1);
        tc_gemm<<<dim3(CD/128, MB, CE),256,TC_SMEM_BYTES>>>(
            CBS, CD, CDF, p_he, w2 + (size_t)l*CE*CDF*CD, (size_t)CDF*CD,
            b2 + (size_t)l*CE*CD, CD,
            nullptr, nullptr, p_moe, nullptr, p_counts, 0);
        combine_k<<<EW,256>>>(p_x, p_moe, p_slot, p_gate);
    }

    ln_k<<<CBS,256>>>(p_x, lnfs, lnfb, (float*)d_out);
}

// round 10
// speedup vs baseline: 1.5408x; 1.1190x over previous
#include <cuda_runtime.h>
#include <math.h>

#define CB 2
#define CT 8
#define CHEADS 12
#define CD 768
#define CDF 3072
#define CE 8
#define CN 196
#define CS 1568
#define CBS 3136           // B*S
#define CBSP 3200          // padded per-expert row stride (25*128)
#define C3D 2304

// smem per stage: raw A[128][36] + raw B[32][136]; two stages (double buffer)
#define SM_A  (128*36)
#define SM_B  (32*136)
#define STG_FLOATS (SM_A + SM_B)
#define TC_SMEM_BYTES (2*STG_FLOATS*4)

// ---------------- scratch (device globals; no allocation allowed) ----------------
__device__ float g_patches[CBS*CD];
__device__ float g_x[CBS*CD];
__device__ float g_h[CBS*CD];
__device__ float g_h2[CBS*CD];
__device__ float g_qkv[CBS*C3D];
__device__ float g_att[CBS*CD];
__device__ float g_he[(size_t)CE*CBSP*CDF];   // expert hidden, slot-indexed (padded)
__device__ float g_moe[(size_t)CE*CBSP*CD];   // expert output, slot-indexed (padded)
__device__ float g_tproj[CB*CD];
__device__ int   g_counts[CE];
__device__ int   g_tok[CE*CBS];              // slot -> token row
__device__ int   g_slot[CBS*2];              // token -> its 2 slots (padded index)
__device__ float g_gate[CBS*2];              // token -> its 2 gates

__device__ __forceinline__ float gelu_t(float x){
    return 0.5f*x*(1.0f + tanhf(0.7978845608028654f*(x + 0.044715f*x*x*x)));
}

// mask-based tf32 hi/lo split: hi keeps exactly tf32's 10 explicit mantissa bits
__device__ __forceinline__ void split1(float v, unsigned& h, unsigned& l){
    unsigned hu = __float_as_uint(v) & 0xFFFFE000u;
    h = hu;
    l = __float_as_uint(v - __uint_as_float(hu));
}

#define MMA_TF32(c, A0,A1,A2,A3, B0,B1) \
    asm volatile("mma.sync.aligned.m16n8k8.row.col.f32.tf32.tf32.f32 " \
        "{%0,%1,%2,%3}, {%4,%5,%6,%7}, {%8,%9}, {%0,%1,%2,%3};" \
        : "+f"((c)[0]),"+f"((c)[1]),"+f"((c)[2]),"+f"((c)[3]) \
        : "r"(A0),"r"(A1),"r"(A2),"r"(A3),"r"(B0),"r"(B1))

// ---------------- patchify ----------------
__global__ __launch_bounds__(256) void patchify_k(const float* __restrict__ video,
                                                  float* __restrict__ out){
    int i = blockIdx.x*256 + threadIdx.x;
    if (i >= CBS*CD) return;
    int r = i / CD, pp = i % CD;
    int b = r / CS, s = r % CS;
    int t = s / CN, pi = s % CN;
    int ph = pi / 14, pw = pi % 14;
    int c = pp >> 8, rem = pp & 255, py = rem >> 4, px = rem & 15;
    size_t vi = ((((size_t)b*CT + t)*3 + c)*224 + (ph*16+py))*224 + (pw*16+px);
    out[i] = video[vi];
}

// ---------------- layernorm ----------------
__global__ __launch_bounds__(256) void ln_k(const float* __restrict__ x,
                                            const float* __restrict__ gs,
                                            const float* __restrict__ gb,
                                            float* __restrict__ out){
    int r = blockIdx.x;
    const float* xr = x + (size_t)r*CD;
    int d = threadIdx.x;
    float v0 = xr[d], v1 = xr[d+256], v2 = xr[d+512];
    float s = v0+v1+v2, sq = v0*v0+v1*v1+v2*v2;
    #pragma unroll
    for (int o=16;o;o>>=1){ s += __shfl_xor_sync(0xffffffffu,s,o); sq += __shfl_xor_sync(0xffffffffu,sq,o); }
    __shared__ float rs[8], rq[8];
    int w = threadIdx.x>>5;
    if ((threadIdx.x&31)==0){ rs[w]=s; rq[w]=sq; }
    __syncthreads();
    float ts=0.f, tq=0.f;
    #pragma unroll
    for (int i=0;i<8;i++){ ts+=rs[i]; tq+=rq[i]; }
    float mean = ts*(1.0f/CD);
    float var  = tq*(1.0f/CD) - mean*mean;
    float rstd = rsqrtf(var + 1e-5f);
    float* orow = out + (size_t)r*CD;
    orow[d]     = (v0-mean)*rstd*gs[d]     + gb[d];
    orow[d+256] = (v1-mean)*rstd*gs[d+256] + gb[d+256];
    orow[d+512] = (v2-mean)*rstd*gs[d+512] + gb[d+512];
}

// =====================================================================
// 3xTF32 mma.sync GEMM v2: raw fp32 in smem (single copy), mask-split at
// fragment load, double-buffered stages, ONE barrier per K-chunk.
// Block 256 thr, tile 128x128, K-chunk 32, warp = 64rows x 32cols. 2 CTAs/SM.
// =====================================================================
__global__ __launch_bounds__(256,2) void tc_gemm(
    int M, int N, int K,
    const float* __restrict__ A,
    const float* __restrict__ Wl, size_t wstride,
    const float* __restrict__ bl, int bstride,
    const float* __restrict__ addFull,
    const float* __restrict__ addRow,
    float* __restrict__ C,
    const int* __restrict__ tok,
    const int* __restrict__ counts,
    int doGelu)
{
    extern __shared__ float smf[];

    const int e = blockIdx.z;
    int Me = M;
    const float* W = Wl;
    const float* bias = bl;
    if (counts){
        Me = counts[e];
        W = Wl + (size_t)e*wstride;
        bias = bl + (size_t)e*bstride;
    }
    const int m0 = blockIdx.y*128;
    if (m0 >= Me) return;
    const int n0 = blockIdx.x*128;
    const int tid = threadIdx.x, wid = tid>>5, lane = tid&31;
    const int wm = (wid>>2)*64;    // 0 / 64
    const int wn = (wid&3)*32;     // 0/32/64/96
    const int g = lane>>2, t4 = lane&3;

    // loader coords
    const int rowA = tid>>1, segA = (tid&1)*16;   // A: 128 rows x 32 cols
    const int rowB = tid>>3, segB = (tid&7)*16;   // B: 32 rows x 128 cols

    size_t arow;
    {
        int mm = m0 + rowA;
        if (tok)         arow = (size_t)tok[e*CBS + (mm < Me ? mm : 0)];
        else if (counts) arow = (size_t)e*CBSP + mm;             // padded scratch, safe
        else             arow = (size_t)(mm < M ? mm : (M-1));
    }
    const float* apBase = A + arow*(size_t)K + segA;
    const float* bpBase = W + (size_t)rowB*N + n0 + segB;

    float acc[4][4][4];
    #pragma unroll
    for (int i=0;i<4;i++)
        #pragma unroll
        for (int j=0;j<4;j++)
            #pragma unroll
            for (int q=0;q<4;q++) acc[i][j][q] = 0.f;

    const int nc = K/32;
    float4 a4[4], b4[4];
    #pragma unroll
    for (int i=0;i<4;i++) a4[i] = *(const float4*)(apBase + i*4);
    #pragma unroll
    for (int i=0;i<4;i++) b4[i] = *(const float4*)(bpBase + i*4);

    for (int c = 0; c < nc; c++){
        float* As = smf + (c&1)*STG_FLOATS;
        float* Bs = As + SM_A;
        // store raw chunk to this stage (safe: stage last computed in iter c-2,
        // and every warp passed the barrier of iter c-1 after finishing it)
        #pragma unroll
        for (int i=0;i<4;i++) *(float4*)(As + rowA*36 + segA + i*4) = a4[i];
        #pragma unroll
        for (int i=0;i<4;i++) *(float4*)(Bs + rowB*136 + segB + i*4) = b4[i];
        __syncthreads();
        // prefetch next chunk (latency hidden by MMA phase)
        if (c+1 < nc){
            const float* ap = apBase + (c+1)*32;
            const float* bp = bpBase + (size_t)(c+1)*32*N;
            #pragma unroll
            for (int i=0;i<4;i++) a4[i] = *(const float4*)(ap + i*4);
            #pragma unroll
            for (int i=0;i<4;i++) b4[i] = *(const float4*)(bp + i*4);
        }
        // compute: 4 k-steps of 8; split hi/lo in registers at load time
        #pragma unroll
        for (int ks=0; ks<4; ks++){
            unsigned ahr[4][4], alr[4][4];
            #pragma unroll
            for (int mi=0;mi<4;mi++){
                int r0 = (wm + mi*16 + g)*36 + ks*8 + t4;
                int r1 = r0 + 8*36;
                split1(As[r0],   ahr[mi][0], alr[mi][0]);
                split1(As[r1],   ahr[mi][1], alr[mi][1]);
                split1(As[r0+4], ahr[mi][2], alr[mi][2]);
                split1(As[r1+4], ahr[mi][3], alr[mi][3]);
            }
            #pragma unroll
            for (int ni=0;ni<4;ni++){
                int b0i = (ks*8 + t4)*136 + wn + ni*8 + g;
                int b1i = b0i + 4*136;
                unsigned bh0, bl0, bh1, bl1;
                split1(Bs[b0i], bh0, bl0);
                split1(Bs[b1i], bh1, bl1);
                #pragma unroll
                for (int mi=0;mi<4;mi++){
                    MMA_TF32(acc[mi][ni], ahr[mi][0],ahr[mi][1],ahr[mi][2],ahr[mi][3], bl0,bl1);
                    MMA_TF32(acc[mi][ni], alr[mi][0],alr[mi][1],alr[mi][2],alr[mi][3], bh0,bh1);
                    MMA_TF32(acc[mi][ni], ahr[mi][0],ahr[mi][1],ahr[mi][2],ahr[mi][3], bh0,bh1);
                }
            }
        }
    }

    // epilogue: direct gmem stores, fused bias/adds/gelu
    #pragma unroll
    for (int mi=0;mi<4;mi++){
        #pragma unroll
        for (int half=0; half<2; half++){
            int mm = m0 + wm + mi*16 + g + half*8;
            if (!counts && mm >= M) continue;
            size_t crow = counts ? ((size_t)e*CBSP + mm) : (size_t)mm;
            float* cp = C + crow*N;
            const float* afp = addFull ? (addFull + crow*N) : (const float*)0;
            const float* arp = addRow  ? (addRow + (size_t)(mm % CS)*N) : (const float*)0;
            #pragma unroll
            for (int ni=0;ni<4;ni++){
                int col = n0 + wn + ni*8 + 2*t4;
                float v0 = acc[mi][ni][half*2+0] + bias[col];
                float v1 = acc[mi][ni][half*2+1] + bias[col+1];
                if (arp){ v0 += arp[col]; v1 += arp[col+1]; }
                if (afp){ v0 += afp[col]; v1 += afp[col+1]; }
                if (doGelu){ v0 = gelu_t(v0); v1 = gelu_t(v1); }
                float2 vv; vv.x = v0; vv.y = v1;
                *(float2*)(cp + col) = vv;
            }
        }
    }
}

// ---------------- flash-style attention (SIMT, unchanged) ----------------
__global__ __launch_bounds__(256) void attn_k(const float* __restrict__ qkv,
                                              const float* __restrict__ tb,
                                              float* __restrict__ out){
    const int h = blockIdx.y, b = blockIdx.z;
    const int q0g = blockIdx.x * 16;
    __shared__ float Qs[16][64];
    __shared__ float Ks[32][65];
    __shared__ float Vs[32][64];
    __shared__ float Ps[8][2][32];
    __shared__ float tbs[15];
    int tid = threadIdx.x, lane = tid & 31, w = tid >> 5;
    if (tid < 15) tbs[tid] = tb[h*15 + tid];
    for (int i = tid; i < 16*64; i += 256){
        int qi = i >> 6, d = i & 63;
        Qs[qi][d] = qkv[(size_t)(b*CS + q0g + qi)*C3D + h*64 + d] * 0.125f;
    }
    __syncthreads();
    const int ql0 = w*2, ql1 = w*2+1;
    const int fq0 = (q0g + ql0)/CN, fq1 = (q0g + ql1)/CN;
    float m0=-1e30f, m1=-1e30f, l0=0.f, l1=0.f;
    float o00=0.f,o01=0.f,o10=0.f,o11=0.f;
    for (int c = 0; c < CS/32; c++){
        __syncthreads();
        for (int i = tid; i < 32*64; i += 256){
            int j = i >> 6, d = i & 63;
            size_t base = (size_t)(b*CS + c*32 + j)*C3D + h*64 + d;
            Ks[j][d] = qkv[base + CD];
            Vs[j][d] = qkv[base + 2*CD];
        }
        __syncthreads();
        int key = c*32 + lane;
        int fk = key/CN;
        float s0=0.f, s1=0.f;
        #pragma unroll
        for (int d=0; d<64; d++){
            float kv = Ks[lane][d];
            s0 += Qs[ql0][d]*kv;
            s1 += Qs[ql1][d]*kv;
        }
        s0 += tbs[fq0 - fk + 7];
        s1 += tbs[fq1 - fk + 7];
        float mx0=s0, mx1=s1;
        #pragma unroll
        for (int o=16;o;o>>=1){ mx0=fmaxf(mx0,__shfl_xor_sync(0xffffffffu,mx0,o)); mx1=fmaxf(mx1,__shfl_xor_sync(0xffffffffu,mx1,o)); }
        float mn0 = fmaxf(m0,mx0), mn1 = fmaxf(m1,mx1);
        float p0 = expf(s0-mn0), p1 = expf(s1-mn1);
        float sp0=p0, sp1=p1;
        #pragma unroll
        for (int o=16;o;o>>=1){ sp0+=__shfl_xor_sync(0xffffffffu,sp0,o); sp1+=__shfl_xor_sync(0xffffffffu,sp1,o); }
        float c0 = expf(m0-mn0), c1 = expf(m1-mn1);
        l0 = l0*c0 + sp0;  l1 = l1*c1 + sp1;
        m0 = mn0; m1 = mn1;
        o00*=c0; o01*=c0; o10*=c1; o11*=c1;
        Ps[w][0][lane]=p0; Ps[w][1][lane]=p1;
        __syncwarp();
        #pragma unroll
        for (int j=0;j<32;j++){
            float v0 = Vs[j][2*lane], v1 = Vs[j][2*lane+1];
            float pa = Ps[w][0][j], pb = Ps[w][1][j];
            o00 += pa*v0; o01 += pa*v1; o10 += pb*v0; o11 += pb*v1;
        }
    }
    float inv0 = 1.f/l0, inv1 = 1.f/l1;
    size_t r0 = (size_t)(b*CS + q0g + ql0)*CD + h*64 + 2*lane;
    size_t r1 = (size_t)(b*CS + q0g + ql1)*CD + h*64 + 2*lane;
    out[r0] = o00*inv0; out[r0+1] = o01*inv0;
    out[r1] = o10*inv1; out[r1+1] = o11*inv1;
}

// ---------------- text projection (tiny) ----------------
__global__ __launch_bounds__(256) void textproj_k(const float* __restrict__ ts,
                                                  const float* __restrict__ wt,
                                                  const float* __restrict__ bt,
                                                  float* __restrict__ out){
    int i = blockIdx.x*256 + threadIdx.x;
    if (i >= CB*CD) return;
    int b = i/CD, d = i%CD;
    float a = bt[d];
    for (int k=0;k<CD;k++) a += ts[b*CD+k]*wt[(size_t)k*CD+d];
    out[i] = a;
}

__global__ void zero8_k(int* c){ if (threadIdx.x < CE) c[threadIdx.x] = 0; }

// ---------------- router ----------------
__global__ __launch_bounds__(256) void router_k(const float* __restrict__ h2,
                                                const float* __restrict__ tproj,
                                                const float* __restrict__ wr,
                                                int* __restrict__ counts,
                                                int* __restrict__ tok_of_slot,
                                                int* __restrict__ slot_of,
                                                float* __restrict__ gatev){
    int w = threadIdx.x >> 5, lane = threadIdx.x & 31;
    int r = blockIdx.x*8 + w;
    int b = r / CS;
    float acc[8] = {};
    for (int d = lane; d < CD; d += 32){
        float rv = h2[(size_t)r*CD + d] + tproj[b*CD + d];
        #pragma unroll
        for (int e=0;e<8;e++) acc[e] += rv * wr[d*8 + e];
    }
    #pragma unroll
    for (int e=0;e<8;e++)
        #pragma unroll
        for (int o=16;o;o>>=1) acc[e] += __shfl_xor_sync(0xffffffffu, acc[e], o);
    if (lane == 0){
        int i0 = 0; float v0 = acc[0];
        #pragma unroll
        for (int e=1;e<8;e++) if (acc[e] > v0){ v0=acc[e]; i0=e; }
        int i1 = -1; float v1 = -1e30f;
        #pragma unroll
        for (int e=0;e<8;e++) if (e!=i0 && acc[e] > v1){ v1=acc[e]; i1=e; }
        float g0 = 1.f/(1.f + expf(v1 - v0));
        float g1 = 1.f - g0;
        int p0 = atomicAdd(&counts[i0], 1);
        tok_of_slot[i0*CBS + p0] = r; slot_of[r*2]   = i0*CBSP + p0; gatev[r*2]   = g0;
        int p1 = atomicAdd(&counts[i1], 1);
        tok_of_slot[i1*CBS + p1] = r; slot_of[r*2+1] = i1*CBSP + p1; gatev[r*2+1] = g1;
    }
}

// ---------------- combine ----------------
__global__ __launch_bounds__(256) void combine_k(float* __restrict__ x,
                                                 const float* __restrict__ moe,
                                                 const int* __restrict__ slot_of,
                                                 const float* __restrict__ gatev){
    int i = blockIdx.x*256 + threadIdx.x;
    if (i >= CBS*CD) return;
    int r = i / CD, d = i % CD;
    float v = x[i];
    v += gatev[r*2]   * moe[(size_t)slot_of[r*2]*CD   + d];
    v += gatev[r*2+1] * moe[(size_t)slot_of[r*2+1]*CD + d];
    x[i] = v;
}

// =============================== host ===============================
extern "C" void kernel_launch(void* const* d_in, const int* in_sizes, int n_in,
                              void* d_out, int out_size){
    const float* video   = (const float*)d_in[0];
    const float* text    = (const float*)d_in[1];
    const float* patch_w = (const float*)d_in[2];
    const float* patch_b = (const float*)d_in[3];
    const float* pos_emb = (const float*)d_in[4];
    const float* ln1s    = (const float*)d_in[5];
    const float* ln1b    = (const float*)d_in[6];
    const float* wqkv    = (const float*)d_in[7];
    const float* bqkv    = (const float*)d_in[8];
    const float* wo      = (const float*)d_in[9];
    const float* bo      = (const float*)d_in[10];
    const float* tbias   = (const float*)d_in[11];
    const float* ln2s    = (const float*)d_in[12];
    const float* ln2b    = (const float*)d_in[13];
    const float* wtext   = (const float*)d_in[14];
    const float* btext   = (const float*)d_in[15];
    const float* wrouter = (const float*)d_in[16];
    const float* w1      = (const float*)d_in[17];
    const float* b1      = (const float*)d_in[18];
    const float* w2      = (const float*)d_in[19];
    const float* b2      = (const float*)d_in[20];
    const float* lnfs    = (const float*)d_in[21];
    const float* lnfb    = (const float*)d_in[22];

    float *p_patches,*p_x,*p_h,*p_h2,*p_qkv,*p_att,*p_he,*p_moe,*p_tproj,*p_gate;
    int *p_counts,*p_tok,*p_slot;
    cudaGetSymbolAddress((void**)&p_patches, g_patches);
    cudaGetSymbolAddress((void**)&p_x,       g_x);
    cudaGetSymbolAddress((void**)&p_h,       g_h);
    cudaGetSymbolAddress((void**)&p_h2,      g_h2);
    cudaGetSymbolAddress((void**)&p_qkv,     g_qkv);
    cudaGetSymbolAddress((void**)&p_att,     g_att);
    cudaGetSymbolAddress((void**)&p_he,      g_he);
    cudaGetSymbolAddress((void**)&p_moe,     g_moe);
    cudaGetSymbolAddress((void**)&p_tproj,   g_tproj);
    cudaGetSymbolAddress((void**)&p_counts,  g_counts);
    cudaGetSymbolAddress((void**)&p_tok,     g_tok);
    cudaGetSymbolAddress((void**)&p_slot,    g_slot);
    cudaGetSymbolAddress((void**)&p_gate,    g_gate);

    cudaFuncSetAttribute(tc_gemm, cudaFuncAttributeMaxDynamicSharedMemorySize, TC_SMEM_BYTES);

    const int EW = (CBS*CD + 255)/256;
    const int MB = (CBS + 127)/128;      // 25

    // embed
    patchify_k<<<EW,256>>>(video, p_patches);
    tc_gemm<<<dim3(CD/128, MB, 1),256,TC_SMEM_BYTES>>>(
        CBS, CD, CD, p_patches, patch_w, 0, patch_b, 0,
        nullptr, pos_emb, p_x, nullptr, nullptr, 0);

    for (int l = 0; l < 4; l++){
        // attention
        ln_k<<<CBS,256>>>(p_x, ln1s + l*CD, ln1b + l*CD, p_h);
        tc_gemm<<<dim3(C3D/128, MB, 1),256,TC_SMEM_BYTES>>>(
            CBS, C3D, CD, p_h, wqkv + (size_t)l*CD*C3D, 0, bqkv + l*C3D, 0,
            nullptr, nullptr, p_qkv, nullptr, nullptr, 0);
        attn_k<<<dim3(CS/16, CHEADS, CB),256>>>(p_qkv, tbias + l*CHEADS*(2*CT-1), p_att);
        tc_gemm<<<dim3(CD/128, MB, 1),256,TC_SMEM_BYTES>>>(
            CBS, CD, CD, p_att, wo + (size_t)l*CD*CD, 0, bo + l*CD, 0,
            p_x, nullptr, p_x, nullptr, nullptr, 0);
        // MoE
        ln_k<<<CBS,256>>>(p_x, ln2s + l*CD, ln2b + l*CD, p_h2);
        textproj_k<<<(CB*CD+255)/256,256>>>(text, wtext + (size_t)l*CD*CD, btext + l*CD, p_tproj);
        zero8_k<<<1,CE>>>(p_counts);
        router_k<<<CBS/8,256>>>(p_h2, p_tproj, wrouter + (size_t)l*CD*CE,
                                p_counts, p_tok, p_slot, p_gate);
        tc_gemm<<<dim3(CDF/128, MB, CE),256,TC_SMEM_BYTES>>>(
            CBS, CDF, CD, p_h2, w1 + (size_t)l*CE*CD*CDF, (size_t)CD*CDF,
            b1 + (size_t)l*CE*CDF, CDF,
            nullptr, nullptr, p_he, p_tok, p_counts, 1);
        tc_gemm<<<dim3(CD/128, MB, CE),256,TC_SMEM_BYTES>>>(
            CBS, CD, CDF, p_he, w2 + (size_t)l*CE*CDF*CD, (size_t)CDF*CD,
            b2 + (size_t)l*CE*CD, CD,
            nullptr, nullptr, p_moe, nullptr, p_counts, 0);
        combine_k<<<EW,256>>>(p_x, p_moe, p_slot, p_gate);
    }

    ln_k<<<CBS,256>>>(p_x, lnfs, lnfb, (float*)d_out);
}

// round 11
// speedup vs baseline: 2.0137x; 1.3069x over previous
#include <cuda_runtime.h>
#include <math.h>

#define CB 2
#define CT 8
#define CHEADS 12
#define CD 768
#define CDF 3072
#define CE 8
#define CN 196
#define CS 1568
#define CBS 3136           // B*S
#define CBSP 3200          // padded per-expert row stride (25*128)
#define C3D 2304

// gemm smem per stage: raw A[128][36] + raw B[32][136]; two stages
#define SM_A  (128*36)
#define SM_B  (32*136)
#define STG_FLOATS (SM_A + SM_B)
#define TC_SMEM_BYTES (2*STG_FLOATS*4)

// attention smem: Ks[64][68] + Vs[64][72] + Ps[64][68] + tbs[16]
#define ATT_KS   0
#define ATT_VS   (64*68)
#define ATT_PS   (64*68 + 64*72)
#define ATT_TBS  (64*68 + 64*72 + 64*68)
#define ATT_SMEM_BYTES ((ATT_TBS + 16)*4)

// ---------------- scratch (device globals; no allocation allowed) ----------------
__device__ float g_patches[CBS*CD];
__device__ float g_x[CBS*CD];
__device__ float g_h[CBS*CD];
__device__ float g_h2[CBS*CD];
__device__ float g_qkv[CBS*C3D];
__device__ float g_att[CBS*CD];
__device__ float g_he[(size_t)CE*CBSP*CDF];   // expert hidden, slot-indexed (padded)
__device__ float g_moe[(size_t)CE*CBSP*CD];   // expert output, slot-indexed (padded)
__device__ float g_tproj[CB*CD];
__device__ int   g_counts[CE];
__device__ int   g_tok[CE*CBS];              // slot -> token row
__device__ int   g_slot[CBS*2];              // token -> its 2 slots (padded index)
__device__ float g_gate[CBS*2];              // token -> its 2 gates

__device__ __forceinline__ float gelu_t(float x){
    return 0.5f*x*(1.0f + tanhf(0.7978845608028654f*(x + 0.044715f*x*x*x)));
}

// mask-based tf32 hi/lo split: hi keeps exactly tf32's 10 explicit mantissa bits
__device__ __forceinline__ void split1(float v, unsigned& h, unsigned& l){
    unsigned hu = __float_as_uint(v) & 0xFFFFE000u;
    h = hu;
    l = __float_as_uint(v - __uint_as_float(hu));
}

#define MMA_TF32(c, A0,A1,A2,A3, B0,B1) \
    asm volatile("mma.sync.aligned.m16n8k8.row.col.f32.tf32.tf32.f32 " \
        "{%0,%1,%2,%3}, {%4,%5,%6,%7}, {%8,%9}, {%0,%1,%2,%3};" \
        : "+f"((c)[0]),"+f"((c)[1]),"+f"((c)[2]),"+f"((c)[3]) \
        : "r"(A0),"r"(A1),"r"(A2),"r"(A3),"r"(B0),"r"(B1))

// ---------------- patchify ----------------
__global__ __launch_bounds__(256) void patchify_k(const float* __restrict__ video,
                                                  float* __restrict__ out){
    int i = blockIdx.x*256 + threadIdx.x;
    if (i >= CBS*CD) return;
    int r = i / CD, pp = i % CD;
    int b = r / CS, s = r % CS;
    int t = s / CN, pi = s % CN;
    int ph = pi / 14, pw = pi % 14;
    int c = pp >> 8, rem = pp & 255, py = rem >> 4, px = rem & 15;
    size_t vi = ((((size_t)b*CT + t)*3 + c)*224 + (ph*16+py))*224 + (pw*16+px);
    out[i] = video[vi];
}

// ---------------- layernorm ----------------
__global__ __launch_bounds__(256) void ln_k(const float* __restrict__ x,
                                            const float* __restrict__ gs,
                                            const float* __restrict__ gb,
                                            float* __restrict__ out){
    int r = blockIdx.x;
    const float* xr = x + (size_t)r*CD;
    int d = threadIdx.x;
    float v0 = xr[d], v1 = xr[d+256], v2 = xr[d+512];
    float s = v0+v1+v2, sq = v0*v0+v1*v1+v2*v2;
    #pragma unroll
    for (int o=16;o;o>>=1){ s += __shfl_xor_sync(0xffffffffu,s,o); sq += __shfl_xor_sync(0xffffffffu,sq,o); }
    __shared__ float rs[8], rq[8];
    int w = threadIdx.x>>5;
    if ((threadIdx.x&31)==0){ rs[w]=s; rq[w]=sq; }
    __syncthreads();
    float ts=0.f, tq=0.f;
    #pragma unroll
    for (int i=0;i<8;i++){ ts+=rs[i]; tq+=rq[i]; }
    float mean = ts*(1.0f/CD);
    float var  = tq*(1.0f/CD) - mean*mean;
    float rstd = rsqrtf(var + 1e-5f);
    float* orow = out + (size_t)r*CD;
    orow[d]     = (v0-mean)*rstd*gs[d]     + gb[d];
    orow[d+256] = (v1-mean)*rstd*gs[d+256] + gb[d+256];
    orow[d+512] = (v2-mean)*rstd*gs[d+512] + gb[d+512];
}

// =====================================================================
// 3xTF32 mma.sync GEMM (unchanged from round 10 winner)
// =====================================================================
__global__ __launch_bounds__(256,2) void tc_gemm(
    int M, int N, int K,
    const float* __restrict__ A,
    const float* __restrict__ Wl, size_t wstride,
    const float* __restrict__ bl, int bstride,
    const float* __restrict__ addFull,
    const float* __restrict__ addRow,
    float* __restrict__ C,
    const int* __restrict__ tok,
    const int* __restrict__ counts,
    int doGelu)
{
    extern __shared__ float smf[];

    const int e = blockIdx.z;
    int Me = M;
    const float* W = Wl;
    const float* bias = bl;
    if (counts){
        Me = counts[e];
        W = Wl + (size_t)e*wstride;
        bias = bl + (size_t)e*bstride;
    }
    const int m0 = blockIdx.y*128;
    if (m0 >= Me) return;
    const int n0 = blockIdx.x*128;
    const int tid = threadIdx.x, wid = tid>>5, lane = tid&31;
    const int wm = (wid>>2)*64;    // 0 / 64
    const int wn = (wid&3)*32;     // 0/32/64/96
    const int g = lane>>2, t4 = lane&3;

    const int rowA = tid>>1, segA = (tid&1)*16;   // A: 128 rows x 32 cols
    const int rowB = tid>>3, segB = (tid&7)*16;   // B: 32 rows x 128 cols

    size_t arow;
    {
        int mm = m0 + rowA;
        if (tok)         arow = (size_t)tok[e*CBS + (mm < Me ? mm : 0)];
        else if (counts) arow = (size_t)e*CBSP + mm;
        else             arow = (size_t)(mm < M ? mm : (M-1));
    }
    const float* apBase = A + arow*(size_t)K + segA;
    const float* bpBase = W + (size_t)rowB*N + n0 + segB;

    float acc[4][4][4];
    #pragma unroll
    for (int i=0;i<4;i++)
        #pragma unroll
        for (int j=0;j<4;j++)
            #pragma unroll
            for (int q=0;q<4;q++) acc[i][j][q] = 0.f;

    const int nc = K/32;
    float4 a4[4], b4[4];
    #pragma unroll
    for (int i=0;i<4;i++) a4[i] = *(const float4*)(apBase + i*4);
    #pragma unroll
    for (int i=0;i<4;i++) b4[i] = *(const float4*)(bpBase + i*4);

    for (int c = 0; c < nc; c++){
        float* As = smf + (c&1)*STG_FLOATS;
        float* Bs = As + SM_A;
        #pragma unroll
        for (int i=0;i<4;i++) *(float4*)(As + rowA*36 + segA + i*4) = a4[i];
        #pragma unroll
        for (int i=0;i<4;i++) *(float4*)(Bs + rowB*136 + segB + i*4) = b4[i];
        __syncthreads();
        if (c+1 < nc){
            const float* ap = apBase + (c+1)*32;
            const float* bp = bpBase + (size_t)(c+1)*32*N;
            #pragma unroll
            for (int i=0;i<4;i++) a4[i] = *(const float4*)(ap + i*4);
            #pragma unroll
            for (int i=0;i<4;i++) b4[i] = *(const float4*)(bp + i*4);
        }
        #pragma unroll
        for (int ks=0; ks<4; ks++){
            unsigned ahr[4][4], alr[4][4];
            #pragma unroll
            for (int mi=0;mi<4;mi++){
                int r0 = (wm + mi*16 + g)*36 + ks*8 + t4;
                int r1 = r0 + 8*36;
                split1(As[r0],   ahr[mi][0], alr[mi][0]);
                split1(As[r1],   ahr[mi][1], alr[mi][1]);
                split1(As[r0+4], ahr[mi][2], alr[mi][2]);
                split1(As[r1+4], ahr[mi][3], alr[mi][3]);
            }
            #pragma unroll
            for (int ni=0;ni<4;ni++){
                int b0i = (ks*8 + t4)*136 + wn + ni*8 + g;
                int b1i = b0i + 4*136;
                unsigned bh0, bl0, bh1, bl1;
                split1(Bs[b0i], bh0, bl0);
                split1(Bs[b1i], bh1, bl1);
                #pragma unroll
                for (int mi=0;mi<4;mi++){
                    MMA_TF32(acc[mi][ni], ahr[mi][0],ahr[mi][1],ahr[mi][2],ahr[mi][3], bl0,bl1);
                    MMA_TF32(acc[mi][ni], alr[mi][0],alr[mi][1],alr[mi][2],alr[mi][3], bh0,bh1);
                    MMA_TF32(acc[mi][ni], ahr[mi][0],ahr[mi][1],ahr[mi][2],ahr[mi][3], bh0,bh1);
                }
            }
        }
    }

    #pragma unroll
    for (int mi=0;mi<4;mi++){
        #pragma unroll
        for (int half=0; half<2; half++){
            int mm = m0 + wm + mi*16 + g + half*8;
            if (!counts && mm >= M) continue;
            size_t crow = counts ? ((size_t)e*CBSP + mm) : (size_t)mm;
            float* cp = C + crow*N;
            const float* afp = addFull ? (addFull + crow*N) : (const float*)0;
            const float* arp = addRow  ? (addRow + (size_t)(mm % CS)*N) : (const float*)0;
            #pragma unroll
            for (int ni=0;ni<4;ni++){
                int col = n0 + wn + ni*8 + 2*t4;
                float v0 = acc[mi][ni][half*2+0] + bias[col];
                float v1 = acc[mi][ni][half*2+1] + bias[col+1];
                if (arp){ v0 += arp[col]; v1 += arp[col+1]; }
                if (afp){ v0 += afp[col]; v1 += afp[col+1]; }
                if (doGelu){ v0 = gelu_t(v0); v1 = gelu_t(v1); }
                float2 vv; vv.x = v0; vv.y = v1;
                *(float2*)(cp + col) = vv;
            }
        }
    }
}

// =====================================================================
// Tensor-core flash attention, 3xTF32.
// Block 128 thr = 4 warps; 64 queries/block, warp owns 16 full rows.
// Key chunks of 64 staged in smem; Q pre-split in registers.
// QK^T and P.V via mma m16n8k8 with mask-split hi/lo (3 terms each).
// =====================================================================
__global__ __launch_bounds__(128) void attn_tc(const float* __restrict__ qkv,
                                               const float* __restrict__ tb,
                                               float* __restrict__ out){
    extern __shared__ float sm[];
    float* Ks  = sm + ATT_KS;    // [64][68]  rows=key, cols=dim
    float* Vs  = sm + ATT_VS;    // [64][72]  rows=key, cols=dh
    float* Ps  = sm + ATT_PS;    // [64][68]  rows=q,   cols=key-in-chunk
    float* tbs = sm + ATT_TBS;   // [15]

    const int h = blockIdx.y, b = blockIdx.z;
    const int q0 = blockIdx.x*64;
    const int tid = threadIdx.x, w = tid>>5, lane = tid&31;
    const int g = lane>>2, t4 = lane&3;
    const int wm = w*16;

    if (tid < 15) tbs[tid] = tb[h*15 + tid];

    const int row0 = q0 + wm + g, row1 = row0 + 8;
    const int r0c = row0 < CS ? row0 : CS-1;
    const int r1c = row1 < CS ? row1 : CS-1;
    const int fq0 = r0c / CN, fq1 = r1c / CN;

    // Q fragments, pre-scaled and pre-split (held whole kernel)
    unsigned qh[8][4], ql[8][4];
    {
        const float* q0p = qkv + (size_t)(b*CS + r0c)*C3D + h*64;
        const float* q1p = qkv + (size_t)(b*CS + r1c)*C3D + h*64;
        #pragma unroll
        for (int ks=0; ks<8; ks++){
            split1(q0p[ks*8+t4]  *0.125f, qh[ks][0], ql[ks][0]);
            split1(q1p[ks*8+t4]  *0.125f, qh[ks][1], ql[ks][1]);
            split1(q0p[ks*8+t4+4]*0.125f, qh[ks][2], ql[ks][2]);
            split1(q1p[ks*8+t4+4]*0.125f, qh[ks][3], ql[ks][3]);
        }
    }

    float o[8][4];
    #pragma unroll
    for (int ni=0;ni<8;ni++){ o[ni][0]=0.f; o[ni][1]=0.f; o[ni][2]=0.f; o[ni][3]=0.f; }
    float m0=-1e30f, m1=-1e30f, l0=0.f, l1=0.f;

    for (int kc = 0; kc < 25; kc++){
        __syncthreads();   // all warps done with previous Ks/Vs
        for (int i = tid; i < 1024; i += 128){
            int j = i>>4, c4 = (i&15)*4;
            int key = kc*64 + j; if (key >= CS) key = CS-1;
            const float* kp = qkv + (size_t)(b*CS + key)*C3D + CD + h*64 + c4;
            *(float4*)(Ks + j*68 + c4) = *(const float4*)kp;
            *(float4*)(Vs + j*72 + c4) = *(const float4*)(kp + CD);
        }
        __syncthreads();

        // --- QK^T ---
        float s[8][4];
        #pragma unroll
        for (int ni=0;ni<8;ni++){ s[ni][0]=0.f; s[ni][1]=0.f; s[ni][2]=0.f; s[ni][3]=0.f; }
        #pragma unroll
        for (int ks=0; ks<8; ks++){
            #pragma unroll
            for (int ni=0; ni<8; ni++){
                int kb = (ni*8 + g)*68 + ks*8 + t4;
                unsigned bh0, bl0, bh1, bl1;
                split1(Ks[kb],   bh0, bl0);
                split1(Ks[kb+4], bh1, bl1);
                MMA_TF32(s[ni], qh[ks][0],qh[ks][1],qh[ks][2],qh[ks][3], bl0,bl1);
                MMA_TF32(s[ni], ql[ks][0],ql[ks][1],ql[ks][2],ql[ks][3], bh0,bh1);
                MMA_TF32(s[ni], qh[ks][0],qh[ks][1],qh[ks][2],qh[ks][3], bh0,bh1);
            }
        }

        // --- bias + mask + online softmax ---
        float mx0=-1e30f, mx1=-1e30f;
        #pragma unroll
        for (int ni=0;ni<8;ni++){
            int k0 = kc*64 + ni*8 + 2*t4;
            if (k0 < CS){
                int fk = k0 / CN;
                s[ni][0] += tbs[fq0 - fk + 7];
                s[ni][2] += tbs[fq1 - fk + 7];
            } else { s[ni][0] = -1e30f; s[ni][2] = -1e30f; }
            if (k0+1 < CS){
                int fk = (k0+1) / CN;
                s[ni][1] += tbs[fq0 - fk + 7];
                s[ni][3] += tbs[fq1 - fk + 7];
            } else { s[ni][1] = -1e30f; s[ni][3] = -1e30f; }
            mx0 = fmaxf(mx0, fmaxf(s[ni][0], s[ni][1]));
            mx1 = fmaxf(mx1, fmaxf(s[ni][2], s[ni][3]));
        }
        mx0 = fmaxf(mx0, __shfl_xor_sync(0xffffffffu, mx0, 1));
        mx0 = fmaxf(mx0, __shfl_xor_sync(0xffffffffu, mx0, 2));
        mx1 = fmaxf(mx1, __shfl_xor_sync(0xffffffffu, mx1, 1));
        mx1 = fmaxf(mx1, __shfl_xor_sync(0xffffffffu, mx1, 2));

        float mn0 = fmaxf(m0, mx0), mn1 = fmaxf(m1, mx1);
        float c0 = __expf(m0 - mn0), c1 = __expf(m1 - mn1);
        float sp0 = 0.f, sp1 = 0.f;
        #pragma unroll
        for (int ni=0;ni<8;ni++){
            s[ni][0] = __expf(s[ni][0] - mn0);
            s[ni][1] = __expf(s[ni][1] - mn0);
            s[ni][2] = __expf(s[ni][2] - mn1);
            s[ni][3] = __expf(s[ni][3] - mn1);
            sp0 += s[ni][0] + s[ni][1];
            sp1 += s[ni][2] + s[ni][3];
            float2 p01; p01.x = s[ni][0]; p01.y = s[ni][1];
            float2 p23; p23.x = s[ni][2]; p23.y = s[ni][3];
            *(float2*)(Ps + (wm+g)*68   + ni*8 + 2*t4) = p01;
            *(float2*)(Ps + (wm+g+8)*68 + ni*8 + 2*t4) = p23;
        }
        sp0 += __shfl_xor_sync(0xffffffffu, sp0, 1);
        sp0 += __shfl_xor_sync(0xffffffffu, sp0, 2);
        sp1 += __shfl_xor_sync(0xffffffffu, sp1, 1);
        sp1 += __shfl_xor_sync(0xffffffffu, sp1, 2);
        l0 = l0*c0 + sp0;  l1 = l1*c1 + sp1;
        m0 = mn0; m1 = mn1;
        #pragma unroll
        for (int ni=0;ni<8;ni++){
            o[ni][0]*=c0; o[ni][1]*=c0; o[ni][2]*=c1; o[ni][3]*=c1;
        }
        __syncwarp();

        // --- P . V ---
        #pragma unroll
        for (int ks=0; ks<8; ks++){
            unsigned ah[4], al[4];
            int p0i = (wm+g)*68 + ks*8 + t4;
            int p1i = p0i + 8*68;
            split1(Ps[p0i],   ah[0], al[0]);
            split1(Ps[p1i],   ah[1], al[1]);
            split1(Ps[p0i+4], ah[2], al[2]);
            split1(Ps[p1i+4], ah[3], al[3]);
            #pragma unroll
            for (int ni=0; ni<8; ni++){
                int vb = (ks*8 + t4)*72 + ni*8 + g;
                unsigned bh0, bl0, bh1, bl1;
                split1(Vs[vb],      bh0, bl0);
                split1(Vs[vb+4*72], bh1, bl1);
                MMA_TF32(o[ni], ah[0],ah[1],ah[2],ah[3], bl0,bl1);
                MMA_TF32(o[ni], al[0],al[1],al[2],al[3], bh0,bh1);
                MMA_TF32(o[ni], ah[0],ah[1],ah[2],ah[3], bh0,bh1);
            }
        }
    }

    float inv0 = 1.f/l0, inv1 = 1.f/l1;
    if (row0 < CS){
        float* op = out + (size_t)(b*CS + row0)*CD + h*64;
        #pragma unroll
        for (int ni=0;ni<8;ni++){
            float2 vv; vv.x = o[ni][0]*inv0; vv.y = o[ni][1]*inv0;
            *(float2*)(op + ni*8 + 2*t4) = vv;
        }
    }
    if (row1 < CS){
        float* op = out + (size_t)(b*CS + row1)*CD + h*64;
        #pragma unroll
        for (int ni=0;ni<8;ni++){
            float2 vv; vv.x = o[ni][2]*inv1; vv.y = o[ni][3]*inv1;
            *(float2*)(op + ni*8 + 2*t4) = vv;
        }
    }
}

// ---------------- text projection (tiny) ----------------
__global__ __launch_bounds__(256) void textproj_k(const float* __restrict__ ts,
                                                  const float* __restrict__ wt,
                                                  const float* __restrict__ bt,
                                                  float* __restrict__ out){
    int i = blockIdx.x*256 + threadIdx.x;
    if (i >= CB*CD) return;
    int b = i/CD, d = i%CD;
    float a = bt[d];
    for (int k=0;k<CD;k++) a += ts[b*CD+k]*wt[(size_t)k*CD+d];
    out[i] = a;
}

__global__ void zero8_k(int* c){ if (threadIdx.x < CE) c[threadIdx.x] = 0; }

// ---------------- router ----------------
__global__ __launch_bounds__(256) void router_k(const float* __restrict__ h2,
                                                const float* __restrict__ tproj,
                                                const float* __restrict__ wr,
                                                int* __restrict__ counts,
                                                int* __restrict__ tok_of_slot,
                                                int* __restrict__ slot_of,
                                                float* __restrict__ gatev){
    int w = threadIdx.x >> 5, lane = threadIdx.x & 31;
    int r = blockIdx.x*8 + w;
    int b = r / CS;
    float acc[8] = {};
    for (int d = lane; d < CD; d += 32){
        float rv = h2[(size_t)r*CD + d] + tproj[b*CD + d];
        #pragma unroll
        for (int e=0;e<8;e++) acc[e] += rv * wr[d*8 + e];
    }
    #pragma unroll
    for (int e=0;e<8;e++)
        #pragma unroll
        for (int o=16;o;o>>=1) acc[e] += __shfl_xor_sync(0xffffffffu, acc[e], o);
    if (lane == 0){
        int i0 = 0; float v0 = acc[0];
        #pragma unroll
        for (int e=1;e<8;e++) if (acc[e] > v0){ v0=acc[e]; i0=e; }
        int i1 = -1; float v1 = -1e30f;
        #pragma unroll
        for (int e=0;e<8;e++) if (e!=i0 && acc[e] > v1){ v1=acc[e]; i1=e; }
        float g0 = 1.f/(1.f + expf(v1 - v0));
        float g1 = 1.f - g0;
        int p0 = atomicAdd(&counts[i0], 1);
        tok_of_slot[i0*CBS + p0] = r; slot_of[r*2]   = i0*CBSP + p0; gatev[r*2]   = g0;
        int p1 = atomicAdd(&counts[i1], 1);
        tok_of_slot[i1*CBS + p1] = r; slot_of[r*2+1] = i1*CBSP + p1; gatev[r*2+1] = g1;
    }
}

// ---------------- combine ----------------
__global__ __launch_bounds__(256) void combine_k(float* __restrict__ x,
                                                 const float* __restrict__ moe,
                                                 const int* __restrict__ slot_of,
                                                 const float* __restrict__ gatev){
    int i = blockIdx.x*256 + threadIdx.x;
    if (i >= CBS*CD) return;
    int r = i / CD, d = i % CD;
    float v = x[i];
    v += gatev[r*2]   * moe[(size_t)slot_of[r*2]*CD   + d];
    v += gatev[r*2+1] * moe[(size_t)slot_of[r*2+1]*CD + d];
    x[i] = v;
}

// =============================== host ===============================
extern "C" void kernel_launch(void* const* d_in, const int* in_sizes, int n_in,
                              void* d_out, int out_size){
    const float* video   = (const float*)d_in[0];
    const float* text    = (const float*)d_in[1];
    const float* patch_w = (const float*)d_in[2];
    const float* patch_b = (const float*)d_in[3];
    const float* pos_emb = (const float*)d_in[4];
    const float* ln1s    = (const float*)d_in[5];
    const float* ln1b    = (const float*)d_in[6];
    const float* wqkv    = (const float*)d_in[7];
    const float* bqkv    = (const float*)d_in[8];
    const float* wo      = (const float*)d_in[9];
    const float* bo      = (const float*)d_in[10];
    const float* tbias   = (const float*)d_in[11];
    const float* ln2s    = (const float*)d_in[12];
    const float* ln2b    = (const float*)d_in[13];
    const float* wtext   = (const float*)d_in[14];
    const float* btext   = (const float*)d_in[15];
    const float* wrouter = (const float*)d_in[16];
    const float* w1      = (const float*)d_in[17];
    const float* b1      = (const float*)d_in[18];
    const float* w2      = (const float*)d_in[19];
    const float* b2      = (const float*)d_in[20];
    const float* lnfs    = (const float*)d_in[21];
    const float* lnfb    = (const float*)d_in[22];

    float *p_patches,*p_x,*p_h,*p_h2,*p_qkv,*p_att,*p_he,*p_moe,*p_tproj,*p_gate;
    int *p_counts,*p_tok,*p_slot;
    cudaGetSymbolAddress((void**)&p_patches, g_patches);
    cudaGetSymbolAddress((void**)&p_x,       g_x);
    cudaGetSymbolAddress((void**)&p_h,       g_h);
    cudaGetSymbolAddress((void**)&p_h2,      g_h2);
    cudaGetSymbolAddress((void**)&p_qkv,     g_qkv);
    cudaGetSymbolAddress((void**)&p_att,     g_att);
    cudaGetSymbolAddress((void**)&p_he,      g_he);
    cudaGetSymbolAddress((void**)&p_moe,     g_moe);
    cudaGetSymbolAddress((void**)&p_tproj,   g_tproj);
    cudaGetSymbolAddress((void**)&p_counts,  g_counts);
    cudaGetSymbolAddress((void**)&p_tok,     g_tok);
    cudaGetSymbolAddress((void**)&p_slot,    g_slot);
    cudaGetSymbolAddress((void**)&p_gate,    g_gate);

    cudaFuncSetAttribute(tc_gemm, cudaFuncAttributeMaxDynamicSharedMemorySize, TC_SMEM_BYTES);
    cudaFuncSetAttribute(attn_tc, cudaFuncAttributeMaxDynamicSharedMemorySize, ATT_SMEM_BYTES);

    const int EW = (CBS*CD + 255)/256;
    const int MB = (CBS + 127)/128;      // 25
    const int QB = (CS + 63)/64;         // 25

    // embed
    patchify_k<<<EW,256>>>(video, p_patches);
    tc_gemm<<<dim3(CD/128, MB, 1),256,TC_SMEM_BYTES>>>(
        CBS, CD, CD, p_patches, patch_w, 0, patch_b, 0,
        nullptr, pos_emb, p_x, nullptr, nullptr, 0);

    for (int l = 0; l < 4; l++){
        // attention
        ln_k<<<CBS,256>>>(p_x, ln1s + l*CD, ln1b + l*CD, p_h);
        tc_gemm<<<dim3(C3D/128, MB, 1),256,TC_SMEM_BYTES>>>(
            CBS, C3D, CD, p_h, wqkv + (size_t)l*CD*C3D, 0, bqkv + l*C3D, 0,
            nullptr, nullptr, p_qkv, nullptr, nullptr, 0);
        attn_tc<<<dim3(QB, CHEADS, CB),128,ATT_SMEM_BYTES>>>(
            p_qkv, tbias + l*CHEADS*(2*CT-1), p_att);
        tc_gemm<<<dim3(CD/128, MB, 1),256,TC_SMEM_BYTES>>>(
            CBS, CD, CD, p_att, wo + (size_t)l*CD*CD, 0, bo + l*CD, 0,
            p_x, nullptr, p_x, nullptr, nullptr, 0);
        // MoE
        ln_k<<<CBS,256>>>(p_x, ln2s + l*CD, ln2b + l*CD, p_h2);
        textproj_k<<<(CB*CD+255)/256,256>>>(text, wtext + (size_t)l*CD*CD, btext + l*CD, p_tproj);
        zero8_k<<<1,CE>>>(p_counts);
        router_k<<<CBS/8,256>>>(p_h2, p_tproj, wrouter + (size_t)l*CD*CE,
                                p_counts, p_tok, p_slot, p_gate);
        tc_gemm<<<dim3(CDF/128, MB, CE),256,TC_SMEM_BYTES>>>(
            CBS, CDF, CD, p_h2, w1 + (size_t)l*CE*CD*CDF, (size_t)CD*CDF,
            b1 + (size_t)l*CE*CDF, CDF,
            nullptr, nullptr, p_he, p_tok, p_counts, 1);
        tc_gemm<<<dim3(CD/128, MB, CE),256,TC_SMEM_BYTES>>>(
            CBS, CD, CDF, p_he, w2 + (size_t)l*CE*CDF*CD, (size_t)CDF*CD,
            b2 + (size_t)l*CE*CD, CD,
            nullptr, nullptr, p_moe, nullptr, p_counts, 0);
        combine_k<<<EW,256>>>(p_x, p_moe, p_slot, p_gate);
    }

    ln_k<<<CBS,256>>>(p_x, lnfs, lnfb, (float*)d_out);
}